// round 13
// baseline (speedup 1.0000x reference)
#include <cuda_runtime.h>
#include <cuda_fp16.h>
#include <cstdint>

#define B_   2
#define N_   2048
#define DIM_ 768
#define H_   12
#define DH_  64
#define M1   (B_*N_)     // 4096
#define NC1  (3*DIM_)    // 2304
#define KH2  768         // u32 (pair) count per GEMM row
#define PITCHB 3072      // bytes per GEMM row

// ---------------- device globals ----------------
__device__ uint32_t g_xl[(long)M1*KH2];      // x limbs interleaved (h,l)
__device__ uint32_t g_wd[(long)NC1*KH2];     // wqkv dup pairs (w,w)
__device__ uint32_t g_pd[(long)DIM_*KH2];    // wp dup pairs (w,w)
__device__ uint32_t g_zl[(long)M1*KH2];      // z limbs interleaved (attention out)
__device__ __half   g_qh[(long)B_*H_*N_*DH_];   // q single-limb [bh][n][64]
__device__ __half   g_kh[(long)B_*H_*N_*DH_];   // k single-limb [bh][m][64]
__device__ __half   g_vt[(long)B_*H_*DH_*N_];   // v^T single-limb [bh][e][m]
__device__ float    g_bq[NC1];
__device__ float    g_bp2[DIM_];

// ---------------- quantizers ----------------
__device__ __forceinline__ float qround8(float x) {        // round-half-even to 2^-8
    float t = __fmaf_rn(x, 256.f, 12582912.f);
    return (t - 12582912.f) * 0.00390625f;
}
__device__ __forceinline__ float q16_8c(float x) {         // with clamp (z saturates)
    float t = __fmaf_rn(x, 256.f, 12582912.f);
    float y = t - 12582912.f;
    y = fminf(fmaxf(y, -32768.f), 32767.f);
    return y * 0.00390625f;
}
__device__ __forceinline__ float q32_16(float x) {
    float t = __fmaf_rn(x, 65536.f, 12582912.f);
    return (t - 12582912.f) * 1.52587890625e-5f;
}
__device__ __forceinline__ uint32_t packu32(__half a, __half b) {
    __half2 t = __halves2half2(a, b);
    return *(uint32_t*)&t;
}

// ---------------- PTX helpers ----------------
__device__ __forceinline__ uint32_t smem_u32(const void* p) {
    uint32_t a;
    asm("{ .reg .u64 t; cvta.to.shared.u64 t, %1; cvt.u32.u64 %0, t; }" : "=r"(a) : "l"(p));
    return a;
}
#define CP_ASYNC16(dst, src) \
    asm volatile("cp.async.cg.shared.global [%0], [%1], 16;" :: "r"(dst), "l"(src) : "memory")
#define CP_COMMIT() asm volatile("cp.async.commit_group;" ::: "memory")
#define CP_WAIT(n)  asm volatile("cp.async.wait_group %0;" :: "n"(n) : "memory")

__device__ __forceinline__ void ldm_x4(uint32_t* r, uint32_t addr) {
    asm volatile("ldmatrix.sync.aligned.m8n8.x4.shared.b16 {%0,%1,%2,%3}, [%4];"
        : "=r"(r[0]), "=r"(r[1]), "=r"(r[2]), "=r"(r[3]) : "r"(addr));
}
__device__ __forceinline__ void mma16816(float* d, const uint32_t* a, const uint32_t* b) {
    asm volatile("mma.sync.aligned.m16n8k16.row.col.f32.f16.f16.f32 "
        "{%0,%1,%2,%3}, {%4,%5,%6,%7}, {%8,%9}, {%0,%1,%2,%3};"
        : "+f"(d[0]), "+f"(d[1]), "+f"(d[2]), "+f"(d[3])
        : "r"(a[0]), "r"(a[1]), "r"(a[2]), "r"(a[3]), "r"(b[0]), "r"(b[1]));
}

// 128B-pitch swizzle: XOR 16B-chunk id with row%8
#define SWZ(row, colb) ((uint32_t)((row)*128 + ((colb) ^ (((row)&7)<<4))))

// ---------------- kernel 1: quantize + limb-split inputs ----------------
__global__ void prep_kernel(const float* __restrict__ x, const float* __restrict__ wqkv,
                            const float* __restrict__ bqkv, const float* __restrict__ wp,
                            const float* __restrict__ bp) {
    long i = (long)blockIdx.x * blockDim.x + threadIdx.x;
    const long NX = (long)M1 * DIM_;
    const long NW = (long)NC1 * DIM_;
    const long NP = (long)DIM_ * DIM_;
    if (i < NX) {
        float v = q32_16(x[i]);
        __half h = __float2half_rn(v);
        __half l = __float2half_rn(v - __half2float(h));
        g_xl[i] = packu32(h, l);
        return;
    }
    i -= NX;
    if (i < NW) {
        __half h = __float2half_rn(qround8(wqkv[i]));   // exact: |w*256| << 2048
        g_wd[i] = packu32(h, h);
        return;
    }
    i -= NW;
    if (i < NP) {
        __half h = __float2half_rn(qround8(wp[i]));
        g_pd[i] = packu32(h, h);
        return;
    }
    i -= NP;
    if (i < NC1) { g_bq[i] = qround8(bqkv[i]); return; }
    i -= NC1;
    if (i < DIM_) g_bp2[i] = qround8(bp[i]);
}

// ---------------- kernel 2: QKV GEMM, CTA 128x256, warp 64x64, 3-stage ----------------
#define QSTG 49152   // A 16KB + B 32KB per stage

__device__ __forceinline__ void qkv_issue(uint32_t st, const char* Ab, const char* Bb,
                                          int kbyte, int tid) {
    #pragma unroll
    for (int i = 0; i < 4; i++) {
        int idx = tid + i * 256;
        int row = idx >> 3, c16 = (idx & 7) << 4;
        CP_ASYNC16(st + SWZ(row, c16), Ab + (long)row * PITCHB + kbyte + c16);
    }
    #pragma unroll
    for (int i = 0; i < 8; i++) {
        int idx = tid + i * 256;
        int row = idx >> 3, c16 = (idx & 7) << 4;
        CP_ASYNC16(st + 16384 + SWZ(row, c16), Bb + (long)row * PITCHB + kbyte + c16);
    }
    CP_COMMIT();
}

__global__ void __launch_bounds__(256, 1) gemm_qkv_tc() {
    extern __shared__ char smem[];
    const uint32_t sb = smem_u32(smem);
    const int tid = threadIdx.x, lane = tid & 31, wid = tid >> 5;
    const int wm = wid & 1, wn = wid >> 1;        // 2 m-halves x 4 n-quarters, warp 64x64
    const int m0 = blockIdx.y * 128;
    const int n0 = blockIdx.x * 256;
    const char* Ab = (const char*)g_xl + (long)m0 * PITCHB;
    const char* Bb = (const char*)g_wd + (long)n0 * PITCHB;

    const int arow_l = (lane & 7) + ((lane >> 3) & 1) * 8;
    const int achk   = (lane >> 4) * 16;
    const int brow_l = (lane & 7) + (lane >> 4) * 8;
    const int bchk   = ((lane >> 3) & 1) * 16;

    float acc[4][8][4];
    #pragma unroll
    for (int f = 0; f < 4; f++)
        #pragma unroll
        for (int j = 0; j < 8; j++)
            #pragma unroll
            for (int e = 0; e < 4; e++) acc[f][j][e] = 0.f;

    qkv_issue(sb + 0 * QSTG, Ab, Bb, 0, tid);
    qkv_issue(sb + 1 * QSTG, Ab, Bb, 128, tid);
    #pragma unroll 1
    for (int g = 0; g < 24; g++) {
        if (g + 2 < 24) { CP_WAIT(1); } else { CP_WAIT(0); }
        __syncthreads();
        if (g + 2 < 24)
            qkv_issue(sb + (uint32_t)((g + 2) % 3) * QSTG, Ab, Bb, (g + 2) * 128, tid);
        uint32_t st = sb + (uint32_t)(g % 3) * QSTG;
        #pragma unroll
        for (int kk = 0; kk < 4; kk++) {
            uint32_t a[4][4];
            #pragma unroll
            for (int f = 0; f < 4; f++)
                ldm_x4(a[f], st + SWZ(wm * 64 + f * 16 + arow_l, kk * 32 + achk));
            #pragma unroll
            for (int gg = 0; gg < 4; gg++) {
                uint32_t b4[4];
                ldm_x4(b4, st + 16384 + SWZ(wn * 64 + gg * 16 + brow_l, kk * 32 + bchk));
                #pragma unroll
                for (int f = 0; f < 4; f++) {
                    mma16816(acc[f][gg * 2 + 0], a[f], b4 + 0);
                    mma16816(acc[f][gg * 2 + 1], a[f], b4 + 2);
                }
            }
        }
    }

    // epilogue: bias + (16,8) quant -> single-limb q/k/v layouts
    const int qr = lane >> 2;
    const int rb = m0 + wm * 64 + qr;
    const int cb = n0 + wn * 64 + (lane & 3) * 2;
    #pragma unroll
    for (int f = 0; f < 4; f++) {
        #pragma unroll
        for (int j = 0; j < 8; j++) {
            int nb = cb + j * 8;                 // even
            float b0 = g_bq[nb], b1 = g_bq[nb + 1];
            int h = nb / 192;
            int rr = nb - h * 192;
            int seg = rr >> 6, e = rr & 63;      // e even
            #pragma unroll
            for (int rs = 0; rs < 2; rs++) {
                int m = rb + f * 16 + rs * 8;
                int bi = m >> 11, nr = m & 2047;
                long bh = bi * H_ + h;
                __half h0 = __float2half_rn(qround8(acc[f][j][rs * 2 + 0] + b0));
                __half h1 = __float2half_rn(qround8(acc[f][j][rs * 2 + 1] + b1));
                if (seg == 0) {
                    *(uint32_t*)(g_qh + (bh * N_ + nr) * DH_ + e) = packu32(h0, h1);
                } else if (seg == 1) {
                    *(uint32_t*)(g_kh + (bh * N_ + nr) * DH_ + e) = packu32(h0, h1);
                } else {
                    g_vt[(bh * DH_ + e) * N_ + nr] = h0;
                    g_vt[(bh * DH_ + e + 1) * N_ + nr] = h1;
                }
            }
        }
    }
}

// ---------------- kernel 4: output projection, M=64 tile, 4-stage ----------------
#define PSTG 24576   // A 8KB + B 16KB per stage

__device__ __forceinline__ void proj_issue(uint32_t st, const char* Ab, const char* Bb,
                                           int kbyte, int tid) {
    #pragma unroll
    for (int i = 0; i < 2; i++) {
        int idx = tid + i * 256;
        int row = idx >> 3, c16 = (idx & 7) << 4;
        CP_ASYNC16(st + SWZ(row, c16), Ab + (long)row * PITCHB + kbyte + c16);
    }
    #pragma unroll
    for (int i = 0; i < 4; i++) {
        int idx = tid + i * 256;
        int row = idx >> 3, c16 = (idx & 7) << 4;
        CP_ASYNC16(st + 8192 + SWZ(row, c16), Bb + (long)row * PITCHB + kbyte + c16);
    }
    CP_COMMIT();
}

__global__ void __launch_bounds__(256, 2) gemm_proj_tc(float* __restrict__ out) {
    extern __shared__ char smem[];
    const uint32_t sb = smem_u32(smem);
    const int tid = threadIdx.x, lane = tid & 31, wid = tid >> 5;
    const int wm = wid & 1, wn = wid >> 1;       // 2 m-groups x 4 n-groups, warp 32x32
    const int m0 = blockIdx.y * 64;
    const int n0 = blockIdx.x * 128;
    const char* Ab = (const char*)g_zl + (long)m0 * PITCHB;
    const char* Bb = (const char*)g_pd + (long)n0 * PITCHB;

    const int arow_l = (lane & 7) + ((lane >> 3) & 1) * 8;
    const int achk   = (lane >> 4) * 16;
    const int brow_l = (lane & 7) + (lane >> 4) * 8;
    const int bchk   = ((lane >> 3) & 1) * 16;

    float acc[2][4][4];
    #pragma unroll
    for (int f = 0; f < 2; f++)
        #pragma unroll
        for (int j = 0; j < 4; j++)
            #pragma unroll
            for (int e = 0; e < 4; e++) acc[f][j][e] = 0.f;

    proj_issue(sb + 0 * PSTG, Ab, Bb, 0, tid);
    proj_issue(sb + 1 * PSTG, Ab, Bb, 128, tid);
    proj_issue(sb + 2 * PSTG, Ab, Bb, 256, tid);
    #pragma unroll 1
    for (int g = 0; g < 24; g++) {
        if (g + 3 < 24) { CP_WAIT(2); } else { CP_WAIT(0); }
        __syncthreads();
        if (g + 3 < 24)
            proj_issue(sb + (uint32_t)((g + 3) & 3) * PSTG, Ab, Bb, (g + 3) * 128, tid);
        uint32_t st = sb + (uint32_t)(g & 3) * PSTG;
        #pragma unroll
        for (int kk = 0; kk < 4; kk++) {
            uint32_t a[2][4];
            #pragma unroll
            for (int f = 0; f < 2; f++)
                ldm_x4(a[f], st + SWZ(wm * 32 + f * 16 + arow_l, kk * 32 + achk));
            #pragma unroll
            for (int gg = 0; gg < 2; gg++) {
                uint32_t b4[4];
                ldm_x4(b4, st + 8192 + SWZ(wn * 32 + gg * 16 + brow_l, kk * 32 + bchk));
                #pragma unroll
                for (int f = 0; f < 2; f++) {
                    mma16816(acc[f][gg * 2 + 0], a[f], b4 + 0);
                    mma16816(acc[f][gg * 2 + 1], a[f], b4 + 2);
                }
            }
        }
    }

    const int rb = m0 + wm * 32 + (lane >> 2);
    const int cb = n0 + wn * 32 + (lane & 3) * 2;
    #pragma unroll
    for (int f = 0; f < 2; f++)
        #pragma unroll
        for (int j = 0; j < 4; j++)
            #pragma unroll
            for (int cs = 0; cs < 2; cs++) {
                int n = cb + j * 8 + cs;
                float bias = g_bp2[n];
                #pragma unroll
                for (int rs = 0; rs < 2; rs++) {
                    int m = rb + f * 16 + rs * 8;
                    out[(long)m * DIM_ + n] = qround8(acc[f][j][rs * 2 + cs] + bias);
                }
            }
}

// ---------------- kernel 3: flash attention, 3-stage KV ring (best-known config) ----------------
// smem: Q [128][64h]=16K | KV 3 stages x (K 8K + V 8K)=48K | Sh 16K | Sl 16K  = 96KB
#define AQ    0u
#define AKV   16384u
#define ASTG  16384u
#define ASH   65536u
#define ASL   81920u
#define ATTN_SMEM 98304

__device__ __forceinline__ void attn_issue(uint32_t stage_base,
        const char* khb, const char* vtb, int kb, int tid) {
    #pragma unroll
    for (int i = 0; i < 2; i++) {
        int idx = tid + i * 256;
        int row = idx >> 3, c16 = (idx & 7) << 4;
        CP_ASYNC16(stage_base + SWZ(row, c16), khb + (long)(kb + row) * 128 + c16);
    }
    #pragma unroll
    for (int i = 0; i < 2; i++) {
        int idx = tid + i * 256;
        int row = idx >> 3, c16 = (idx & 7) << 4;
        CP_ASYNC16(stage_base + 8192 + SWZ(row, c16), vtb + (long)row * (N_ * 2) + kb * 2 + c16);
    }
    CP_COMMIT();
}

__global__ void __launch_bounds__(256, 2) attn_tc_kernel() {
    extern __shared__ char smem[];
    const uint32_t sb = smem_u32(smem);
    const int tid = threadIdx.x;
    const int lane = tid & 31, wid = tid >> 5;
    const int wm = wid & 3, wn = wid >> 2;   // wm: q-row group of 32; wn: col group
    const int bh = blockIdx.y;
    const int q0 = blockIdx.x * 128;

    const char* qhb = (const char*)(g_qh + ((long)bh * N_ + q0) * DH_);
    const char* khb = (const char*)(g_kh + (long)bh * N_ * DH_);
    const char* vtb = (const char*)(g_vt + (long)bh * DH_ * N_);

    #pragma unroll
    for (int i = 0; i < 4; i++) {
        int idx = tid + i * 256;
        int row = idx >> 3, c16 = (idx & 7) << 4;
        CP_ASYNC16(sb + AQ + SWZ(row, c16), qhb + (long)row * 128 + c16);
    }
    attn_issue(sb + AKV + 0 * ASTG, khb, vtb, 0, tid);
    attn_issue(sb + AKV + 1 * ASTG, khb, vtb, 64, tid);

    const int arow_l = (lane & 7) + ((lane >> 3) & 1) * 8;
    const int achk   = (lane >> 4) * 16;
    const int brow_l = (lane & 7) + (lane >> 4) * 8;
    const int bchk   = ((lane >> 3) & 1) * 16;
    const int qr     = lane >> 2;
    const int qc     = (lane & 3) * 2;

    uint32_t qfrag[4][2][4];   // Q fragments, loop-invariant (loaded at it==0)
    float zacc[2][4][4];
    #pragma unroll
    for (int f = 0; f < 2; f++)
        #pragma unroll
        for (int j = 0; j < 4; j++)
            #pragma unroll
            for (int e = 0; e < 4; e++) zacc[f][j][e] = 0.f;

    #pragma unroll 1
    for (int it = 0; it < 32; it++) {
        if (it + 2 < 32) { CP_WAIT(1); } else { CP_WAIT(0); }
        __syncthreads();
        if (it + 2 < 32)
            attn_issue(sb + AKV + (uint32_t)((it + 2) % 3) * ASTG, khb, vtb, (it + 2) * 64, tid);
        const uint32_t sK = sb + AKV + (uint32_t)(it % 3) * ASTG;
        const uint32_t sV = sK + 8192u;

        if (it == 0) {
            #pragma unroll
            for (int kk = 0; kk < 4; kk++)
                #pragma unroll
                for (int f = 0; f < 2; f++)
                    ldm_x4(qfrag[kk][f], sb + AQ + SWZ(wm * 32 + f * 16 + arow_l, kk * 32 + achk));
        }

        // ---- phase 1: s = q x k^T (Q frags in regs) ----
        float sacc[2][4][4];
        #pragma unroll
        for (int f = 0; f < 2; f++)
            #pragma unroll
            for (int j = 0; j < 4; j++)
                #pragma unroll
                for (int e = 0; e < 4; e++) sacc[f][j][e] = 0.f;
        #pragma unroll
        for (int kk = 0; kk < 4; kk++) {
            #pragma unroll
            for (int g = 0; g < 2; g++) {
                uint32_t b4[4];
                ldm_x4(b4, sK + SWZ(wn * 32 + g * 16 + brow_l, kk * 32 + bchk));
                #pragma unroll
                for (int f = 0; f < 2; f++) {
                    mma16816(sacc[f][g * 2 + 0], qfrag[kk][f], b4 + 0);
                    mma16816(sacc[f][g * 2 + 1], qfrag[kk][f], b4 + 2);
                }
            }
        }
        // quantize s -> 2 limb planes, packed u32 stores
        #pragma unroll
        for (int f = 0; f < 2; f++)
            #pragma unroll
            for (int j = 0; j < 4; j++)
                #pragma unroll
                for (int rs = 0; rs < 2; rs++) {
                    int row = wm * 32 + f * 16 + qr + rs * 8;
                    int colb = (wn * 32 + j * 8 + qc) * 2;
                    float s0 = qround8(sacc[f][j][rs * 2 + 0]);
                    float s1 = qround8(sacc[f][j][rs * 2 + 1]);
                    __half h0 = __float2half_rn(s0);
                    __half h1 = __float2half_rn(s1);
                    __half l0 = __float2half_rn(s0 - __half2float(h0));
                    __half l1 = __float2half_rn(s1 - __half2float(h1));
                    *(uint32_t*)(smem + ASH + SWZ(row, colb)) = packu32(h0, h1);
                    *(uint32_t*)(smem + ASL + SWZ(row, colb)) = packu32(l0, l1);
                }
        __syncthreads();

        // ---- phase 2: z += s x v; V frags shared across both s-limb planes ----
        #pragma unroll
        for (int kk = 0; kk < 4; kk++) {
            uint32_t bv[2][4];
            #pragma unroll
            for (int g = 0; g < 2; g++)
                ldm_x4(bv[g], sV + SWZ(wn * 32 + g * 16 + brow_l, kk * 32 + bchk));
            #pragma unroll
            for (int plane = 0; plane < 2; plane++) {
                uint32_t sp = sb + (plane ? ASL : ASH);
                uint32_t a[2][4];
                #pragma unroll
                for (int f = 0; f < 2; f++)
                    ldm_x4(a[f], sp + SWZ(wm * 32 + f * 16 + arow_l, kk * 32 + achk));
                #pragma unroll
                for (int g = 0; g < 2; g++)
                    #pragma unroll
                    for (int f = 0; f < 2; f++) {
                        mma16816(zacc[f][g * 2 + 0], a[f], bv[g] + 0);
                        mma16816(zacc[f][g * 2 + 1], a[f], bv[g] + 2);
                    }
            }
        }
    }

    // epilogue: quantize z (clamped), limb-split, interleaved layout for proj
    const int b = bh / H_, h = bh - b * H_;
    #pragma unroll
    for (int f = 0; f < 2; f++)
        #pragma unroll
        for (int j = 0; j < 4; j++)
            #pragma unroll
            for (int rs = 0; rs < 2; rs++)
                #pragma unroll
                for (int cs = 0; cs < 2; cs++) {
                    int n = q0 + wm * 32 + f * 16 + qr + rs * 8;
                    int e = wn * 32 + j * 8 + qc + cs;
                    float zq = q16_8c(zacc[f][j][rs * 2 + cs]);
                    __half hh = __float2half_rn(zq);
                    __half ll = __float2half_rn(zq - __half2float(hh));
                    g_zl[((long)(b * N_ + n)) * KH2 + h * DH_ + e] = packu32(hh, ll);
                }
}

// ---------------- launch ----------------
extern "C" void kernel_launch(void* const* d_in, const int* in_sizes, int n_in,
                              void* d_out, int out_size) {
    const float* q_in = (const float*)d_in[0];
    const float* wqkv = (const float*)d_in[1];
    const float* bqkv = (const float*)d_in[2];
    const float* wp   = (const float*)d_in[3];
    const float* bp   = (const float*)d_in[4];
    float* out = (float*)d_out;

    const long total = (long)M1 * DIM_ + (long)NC1 * DIM_ + (long)DIM_ * DIM_ + NC1 + DIM_;
    prep_kernel<<<(unsigned)((total + 255) / 256), 256>>>(q_in, wqkv, bqkv, wp, bp);

    const int qkv_smem = 3 * QSTG;   // 147456 (1 CTA/SM; smem-BW-bound so occ is moot)
    cudaFuncSetAttribute(gemm_qkv_tc, cudaFuncAttributeMaxDynamicSharedMemorySize, qkv_smem);
    gemm_qkv_tc<<<dim3(NC1 / 256, M1 / 128), 256, qkv_smem>>>();        // (9, 32)

    cudaFuncSetAttribute(attn_tc_kernel, cudaFuncAttributeMaxDynamicSharedMemorySize, ATTN_SMEM);
    attn_tc_kernel<<<dim3(N_ / 128, B_ * H_), 256, ATTN_SMEM>>>();      // (16, 24)

    const int proj_smem = 4 * PSTG;   // 98304 -> 2 CTA/SM
    cudaFuncSetAttribute(gemm_proj_tc, cudaFuncAttributeMaxDynamicSharedMemorySize, proj_smem);
    gemm_proj_tc<<<dim3(DIM_ / 128, M1 / 64), 256, proj_smem>>>(out);   // (6, 64)
}

// round 15
// speedup vs baseline: 1.0575x; 1.0575x over previous
#include <cuda_runtime.h>
#include <cuda_fp16.h>
#include <cstdint>

#define B_   2
#define N_   2048
#define DIM_ 768
#define H_   12
#define DH_  64
#define M1   (B_*N_)     // 4096
#define NC1  (3*DIM_)    // 2304
#define KH2  768         // u32 (pair) count per GEMM row
#define PITCHB 3072      // bytes per GEMM row

// ---------------- device globals ----------------
__device__ uint32_t g_xl[(long)M1*KH2];      // x limbs interleaved (h,l)
__device__ uint32_t g_wd[(long)NC1*KH2];     // wqkv dup pairs (w,w)
__device__ uint32_t g_pd[(long)DIM_*KH2];    // wp dup pairs (w,w)
__device__ uint32_t g_zl[(long)M1*KH2];      // z limbs interleaved (attention out)
__device__ __half   g_qh[(long)B_*H_*N_*DH_];   // q single-limb [bh][n][64]
__device__ __half   g_kh[(long)B_*H_*N_*DH_];   // k single-limb [bh][m][64]
__device__ __half   g_vt[(long)B_*H_*DH_*N_];   // v^T single-limb [bh][e][m]
__device__ float    g_bq[NC1];
__device__ float    g_bp2[DIM_];

// ---------------- quantizers ----------------
__device__ __forceinline__ float qround8(float x) {        // round-half-even to 2^-8
    float t = __fmaf_rn(x, 256.f, 12582912.f);
    return (t - 12582912.f) * 0.00390625f;
}
__device__ __forceinline__ float q16_8c(float x) {         // with clamp (z saturates)
    float t = __fmaf_rn(x, 256.f, 12582912.f);
    float y = t - 12582912.f;
    y = fminf(fmaxf(y, -32768.f), 32767.f);
    return y * 0.00390625f;
}
__device__ __forceinline__ float q32_16(float x) {
    float t = __fmaf_rn(x, 65536.f, 12582912.f);
    return (t - 12582912.f) * 1.52587890625e-5f;
}
__device__ __forceinline__ uint32_t packu32(__half a, __half b) {
    __half2 t = __halves2half2(a, b);
    return *(uint32_t*)&t;
}
__device__ __forceinline__ uint32_t xlimb(float xv) {      // q32_16 then fp16 limb pair
    float v = q32_16(xv);
    __half h = __float2half_rn(v);
    __half l = __float2half_rn(v - __half2float(h));
    return packu32(h, l);
}
__device__ __forceinline__ uint32_t wdup(float wv) {       // q16_8 then dup pair
    __half h = __float2half_rn(qround8(wv));
    return packu32(h, h);
}

// ---------------- PTX helpers ----------------
__device__ __forceinline__ uint32_t smem_u32(const void* p) {
    uint32_t a;
    asm("{ .reg .u64 t; cvta.to.shared.u64 t, %1; cvt.u32.u64 %0, t; }" : "=r"(a) : "l"(p));
    return a;
}
#define CP_ASYNC16(dst, src) \
    asm volatile("cp.async.cg.shared.global [%0], [%1], 16;" :: "r"(dst), "l"(src) : "memory")
#define CP_COMMIT() asm volatile("cp.async.commit_group;" ::: "memory")
#define CP_WAIT(n)  asm volatile("cp.async.wait_group %0;" :: "n"(n) : "memory")

__device__ __forceinline__ void ldm_x4(uint32_t* r, uint32_t addr) {
    asm volatile("ldmatrix.sync.aligned.m8n8.x4.shared.b16 {%0,%1,%2,%3}, [%4];"
        : "=r"(r[0]), "=r"(r[1]), "=r"(r[2]), "=r"(r[3]) : "r"(addr));
}
__device__ __forceinline__ void mma16816(float* d, const uint32_t* a, const uint32_t* b) {
    asm volatile("mma.sync.aligned.m16n8k16.row.col.f32.f16.f16.f32 "
        "{%0,%1,%2,%3}, {%4,%5,%6,%7}, {%8,%9}, {%0,%1,%2,%3};"
        : "+f"(d[0]), "+f"(d[1]), "+f"(d[2]), "+f"(d[3])
        : "r"(a[0]), "r"(a[1]), "r"(a[2]), "r"(a[3]), "r"(b[0]), "r"(b[1]));
}

// 128B-pitch swizzle: XOR 16B-chunk id with row%8
#define SWZ(row, colb) ((uint32_t)((row)*128 + ((colb) ^ (((row)&7)<<4))))

// ---------------- kernel 1: vectorized quantize + limb-split ----------------
__global__ void prep_kernel(const float* __restrict__ x, const float* __restrict__ wqkv,
                            const float* __restrict__ bqkv, const float* __restrict__ wp,
                            const float* __restrict__ bp) {
    long i = (long)blockIdx.x * blockDim.x + threadIdx.x;
    const long NX4 = (long)M1 * DIM_ / 4;
    const long NW4 = (long)NC1 * DIM_ / 4;
    const long NP4 = (long)DIM_ * DIM_ / 4;
    if (i < NX4) {
        float4 v = ((const float4*)x)[i];
        uint4 o;
        o.x = xlimb(v.x); o.y = xlimb(v.y); o.z = xlimb(v.z); o.w = xlimb(v.w);
        ((uint4*)g_xl)[i] = o;
        return;
    }
    i -= NX4;
    if (i < NW4) {
        float4 v = ((const float4*)wqkv)[i];
        uint4 o;
        o.x = wdup(v.x); o.y = wdup(v.y); o.z = wdup(v.z); o.w = wdup(v.w);
        ((uint4*)g_wd)[i] = o;
        return;
    }
    i -= NW4;
    if (i < NP4) {
        float4 v = ((const float4*)wp)[i];
        uint4 o;
        o.x = wdup(v.x); o.y = wdup(v.y); o.z = wdup(v.z); o.w = wdup(v.w);
        ((uint4*)g_pd)[i] = o;
        return;
    }
    i -= NP4;
    if (i < NC1 / 4) {
        float4 v = ((const float4*)bqkv)[i];
        float4 o;
        o.x = qround8(v.x); o.y = qround8(v.y); o.z = qround8(v.z); o.w = qround8(v.w);
        ((float4*)g_bq)[i] = o;
        return;
    }
    i -= NC1 / 4;
    if (i < DIM_ / 4) {
        float4 v = ((const float4*)bp)[i];
        float4 o;
        o.x = qround8(v.x); o.y = qround8(v.y); o.z = qround8(v.z); o.w = qround8(v.w);
        ((float4*)g_bp2)[i] = o;
    }
}

// ---------------- QKV GEMM core: 3-stage single-sync (M=128 tile) ----------------
#define GSTG 32768   // A 16KB + B 16KB per stage
struct AccTile { float a[2][8][4]; };

__device__ __forceinline__ void gemm_issue(uint32_t st, const char* Ab, const char* Bb,
                                           int kbyte, int tid) {
    #pragma unroll
    for (int i = 0; i < 4; i++) {
        int idx = tid + i * 256;
        int row = idx >> 3, c16 = (idx & 7) << 4;
        CP_ASYNC16(st + SWZ(row, c16), Ab + (long)row * PITCHB + kbyte + c16);
    }
    #pragma unroll
    for (int i = 0; i < 4; i++) {
        int idx = tid + i * 256;
        int row = idx >> 3, c16 = (idx & 7) << 4;
        CP_ASYNC16(st + 16384 + SWZ(row, c16), Bb + (long)row * PITCHB + kbyte + c16);
    }
    CP_COMMIT();
}

__device__ __forceinline__ void gemm_compute(uint32_t st, AccTile& acc, int wm, int wn, int lane) {
    const int arow_l = (lane & 7) + ((lane >> 3) & 1) * 8;
    const int achk   = (lane >> 4) * 16;
    const int brow_l = (lane & 7) + (lane >> 4) * 8;
    const int bchk   = ((lane >> 3) & 1) * 16;
    #pragma unroll
    for (int kk = 0; kk < 4; kk++) {
        uint32_t a[2][4];
        #pragma unroll
        for (int f = 0; f < 2; f++)
            ldm_x4(a[f], st + SWZ(wm * 32 + f * 16 + arow_l, kk * 32 + achk));
        #pragma unroll
        for (int g = 0; g < 4; g++) {
            uint32_t b4[4];
            ldm_x4(b4, st + 16384 + SWZ(wn * 64 + g * 16 + brow_l, kk * 32 + bchk));
            #pragma unroll
            for (int f = 0; f < 2; f++) {
                mma16816(acc.a[f][g * 2 + 0], a[f], b4 + 0);
                mma16816(acc.a[f][g * 2 + 1], a[f], b4 + 2);
            }
        }
    }
}

__device__ __forceinline__ void gemm_main(const char* Ab, const char* Bb,
                                          AccTile& acc, char* smem, int tid) {
    uint32_t sb = smem_u32(smem);
    const int lane = tid & 31, wid = tid >> 5;
    const int wm = wid & 3, wn = wid >> 2;
    #pragma unroll
    for (int f = 0; f < 2; f++)
        #pragma unroll
        for (int j = 0; j < 8; j++)
            #pragma unroll
            for (int e = 0; e < 4; e++) acc.a[f][j][e] = 0.f;

    gemm_issue(sb + 0 * GSTG, Ab, Bb, 0, tid);
    gemm_issue(sb + 1 * GSTG, Ab, Bb, 128, tid);
    #pragma unroll 1
    for (int g = 0; g < 24; g++) {
        if (g + 2 < 24) { CP_WAIT(1); } else { CP_WAIT(0); }
        __syncthreads();
        if (g + 2 < 24)
            gemm_issue(sb + (uint32_t)((g + 2) % 3) * GSTG, Ab, Bb, (g + 2) * 128, tid);
        gemm_compute(sb + (uint32_t)(g % 3) * GSTG, acc, wm, wn, lane);
    }
}

// ---------------- kernel 2: QKV projection + single-limb q/k/v epilogue ----------------
__global__ void __launch_bounds__(256, 2) gemm_qkv_tc() {
    extern __shared__ char smem[];
    const int tid = threadIdx.x;
    const int m0 = blockIdx.y * 128;
    const int n0 = blockIdx.x * 128;
    AccTile acc;
    gemm_main((const char*)g_xl + (long)m0 * PITCHB,
              (const char*)g_wd + (long)n0 * PITCHB, acc, smem, tid);

    const int wid = tid >> 5, lane = tid & 31;
    const int wm = wid & 3, wn = wid >> 2;
    const int rb = m0 + wm * 32 + (lane >> 2);
    const int cb = n0 + wn * 64 + (lane & 3) * 2;
    #pragma unroll
    for (int f = 0; f < 2; f++) {
        #pragma unroll
        for (int j = 0; j < 8; j++) {
            int nb = cb + j * 8;                 // even
            float b0 = g_bq[nb], b1 = g_bq[nb + 1];
            int h = nb / 192;
            int rr = nb - h * 192;
            int seg = rr >> 6, e = rr & 63;      // e even
            #pragma unroll
            for (int rs = 0; rs < 2; rs++) {
                int m = rb + f * 16 + rs * 8;
                int bi = m >> 11, nr = m & 2047;
                long bh = bi * H_ + h;
                __half h0 = __float2half_rn(qround8(acc.a[f][j][rs * 2 + 0] + b0));
                __half h1 = __float2half_rn(qround8(acc.a[f][j][rs * 2 + 1] + b1));
                if (seg == 0) {
                    *(uint32_t*)(g_qh + (bh * N_ + nr) * DH_ + e) = packu32(h0, h1);
                } else if (seg == 1) {
                    *(uint32_t*)(g_kh + (bh * N_ + nr) * DH_ + e) = packu32(h0, h1);
                } else {
                    g_vt[(bh * DH_ + e) * N_ + nr] = h0;
                    g_vt[(bh * DH_ + e + 1) * N_ + nr] = h1;
                }
            }
        }
    }
}

// ---------------- kernel 4: output projection, M=64 tile, 4-stage ----------------
#define PSTG 24576   // A 8KB + B 16KB per stage

__device__ __forceinline__ void proj_issue(uint32_t st, const char* Ab, const char* Bb,
                                           int kbyte, int tid) {
    #pragma unroll
    for (int i = 0; i < 2; i++) {
        int idx = tid + i * 256;
        int row = idx >> 3, c16 = (idx & 7) << 4;
        CP_ASYNC16(st + SWZ(row, c16), Ab + (long)row * PITCHB + kbyte + c16);
    }
    #pragma unroll
    for (int i = 0; i < 4; i++) {
        int idx = tid + i * 256;
        int row = idx >> 3, c16 = (idx & 7) << 4;
        CP_ASYNC16(st + 8192 + SWZ(row, c16), Bb + (long)row * PITCHB + kbyte + c16);
    }
    CP_COMMIT();
}

__global__ void __launch_bounds__(256, 2) gemm_proj_tc(float* __restrict__ out) {
    extern __shared__ char smem[];
    const uint32_t sb = smem_u32(smem);
    const int tid = threadIdx.x, lane = tid & 31, wid = tid >> 5;
    const int wm = wid & 1, wn = wid >> 1;       // 2 m-groups x 4 n-groups, warp 32x32
    const int m0 = blockIdx.y * 64;
    const int n0 = blockIdx.x * 128;
    const char* Ab = (const char*)g_zl + (long)m0 * PITCHB;
    const char* Bb = (const char*)g_pd + (long)n0 * PITCHB;

    const int arow_l = (lane & 7) + ((lane >> 3) & 1) * 8;
    const int achk   = (lane >> 4) * 16;
    const int brow_l = (lane & 7) + (lane >> 4) * 8;
    const int bchk   = ((lane >> 3) & 1) * 16;

    float acc[2][4][4];
    #pragma unroll
    for (int f = 0; f < 2; f++)
        #pragma unroll
        for (int j = 0; j < 4; j++)
            #pragma unroll
            for (int e = 0; e < 4; e++) acc[f][j][e] = 0.f;

    proj_issue(sb + 0 * PSTG, Ab, Bb, 0, tid);
    proj_issue(sb + 1 * PSTG, Ab, Bb, 128, tid);
    proj_issue(sb + 2 * PSTG, Ab, Bb, 256, tid);
    #pragma unroll 1
    for (int g = 0; g < 24; g++) {
        if (g + 3 < 24) { CP_WAIT(2); } else { CP_WAIT(0); }
        __syncthreads();
        if (g + 3 < 24)
            proj_issue(sb + (uint32_t)((g + 3) & 3) * PSTG, Ab, Bb, (g + 3) * 128, tid);
        uint32_t st = sb + (uint32_t)(g & 3) * PSTG;
        #pragma unroll
        for (int kk = 0; kk < 4; kk++) {
            uint32_t a[2][4];
            #pragma unroll
            for (int f = 0; f < 2; f++)
                ldm_x4(a[f], st + SWZ(wm * 32 + f * 16 + arow_l, kk * 32 + achk));
            #pragma unroll
            for (int gg = 0; gg < 2; gg++) {
                uint32_t b4[4];
                ldm_x4(b4, st + 8192 + SWZ(wn * 32 + gg * 16 + brow_l, kk * 32 + bchk));
                #pragma unroll
                for (int f = 0; f < 2; f++) {
                    mma16816(acc[f][gg * 2 + 0], a[f], b4 + 0);
                    mma16816(acc[f][gg * 2 + 1], a[f], b4 + 2);
                }
            }
        }
    }

    const int rb = m0 + wm * 32 + (lane >> 2);
    const int cb = n0 + wn * 32 + (lane & 3) * 2;
    #pragma unroll
    for (int f = 0; f < 2; f++)
        #pragma unroll
        for (int j = 0; j < 4; j++)
            #pragma unroll
            for (int cs = 0; cs < 2; cs++) {
                int n = cb + j * 8 + cs;
                float bias = g_bp2[n];
                #pragma unroll
                for (int rs = 0; rs < 2; rs++) {
                    int m = rb + f * 16 + rs * 8;
                    out[(long)m * DIM_ + n] = qround8(acc[f][j][rs * 2 + cs] + bias);
                }
            }
}

// ---------------- kernel 3: flash attention, 4-stage KV ring ----------------
// smem: Q 16K | KV 4 stages x (K 8K + V 8K) = 64K | Sh 16K | Sl 16K  = 112KB (2 CTA/SM)
#define AQ    0u
#define AKV   16384u
#define ASTG  16384u
#define ASH   81920u
#define ASL   98304u
#define ATTN_SMEM 114688

__device__ __forceinline__ void attn_issue(uint32_t stage_base,
        const char* khb, const char* vtb, int kb, int tid) {
    #pragma unroll
    for (int i = 0; i < 2; i++) {
        int idx = tid + i * 256;
        int row = idx >> 3, c16 = (idx & 7) << 4;
        CP_ASYNC16(stage_base + SWZ(row, c16), khb + (long)(kb + row) * 128 + c16);
    }
    #pragma unroll
    for (int i = 0; i < 2; i++) {
        int idx = tid + i * 256;
        int row = idx >> 3, c16 = (idx & 7) << 4;
        CP_ASYNC16(stage_base + 8192 + SWZ(row, c16), vtb + (long)row * (N_ * 2) + kb * 2 + c16);
    }
    CP_COMMIT();
}

__global__ void __launch_bounds__(256, 2) attn_tc_kernel() {
    extern __shared__ char smem[];
    const uint32_t sb = smem_u32(smem);
    const int tid = threadIdx.x;
    const int lane = tid & 31, wid = tid >> 5;
    const int wm = wid & 3, wn = wid >> 2;   // wm: q-row group of 32; wn: col group
    const int bh = blockIdx.y;
    const int q0 = blockIdx.x * 128;

    const char* qhb = (const char*)(g_qh + ((long)bh * N_ + q0) * DH_);
    const char* khb = (const char*)(g_kh + (long)bh * N_ * DH_);
    const char* vtb = (const char*)(g_vt + (long)bh * DH_ * N_);

    // prologue: Q tile (joins group 0) + stages 0,1,2
    #pragma unroll
    for (int i = 0; i < 4; i++) {
        int idx = tid + i * 256;
        int row = idx >> 3, c16 = (idx & 7) << 4;
        CP_ASYNC16(sb + AQ + SWZ(row, c16), qhb + (long)row * 128 + c16);
    }
    attn_issue(sb + AKV + 0 * ASTG, khb, vtb, 0, tid);
    attn_issue(sb + AKV + 1 * ASTG, khb, vtb, 64, tid);
    attn_issue(sb + AKV + 2 * ASTG, khb, vtb, 128, tid);

    const int arow_l = (lane & 7) + ((lane >> 3) & 1) * 8;
    const int achk   = (lane >> 4) * 16;
    const int brow_l = (lane & 7) + (lane >> 4) * 8;
    const int bchk   = ((lane >> 3) & 1) * 16;
    const int qr     = lane >> 2;
    const int qc     = (lane & 3) * 2;

    uint32_t qfrag[4][2][4];   // Q fragments, loop-invariant (loaded at it==0)
    float zacc[2][4][4];
    #pragma unroll
    for (int f = 0; f < 2; f++)
        #pragma unroll
        for (int j = 0; j < 4; j++)
            #pragma unroll
            for (int e = 0; e < 4; e++) zacc[f][j][e] = 0.f;

    #pragma unroll 1
    for (int it = 0; it < 32; it++) {
        if (it + 3 < 32) { CP_WAIT(2); } else { CP_WAIT(0); }
        __syncthreads();    // stage it ready; all warps done with stage it-1
        if (it + 3 < 32)
            attn_issue(sb + AKV + (uint32_t)((it + 3) & 3) * ASTG, khb, vtb, (it + 3) * 64, tid);
        const uint32_t sK = sb + AKV + (uint32_t)(it & 3) * ASTG;
        const uint32_t sV = sK + 8192u;

        if (it == 0) {
            #pragma unroll
            for (int kk = 0; kk < 4; kk++)
                #pragma unroll
                for (int f = 0; f < 2; f++)
                    ldm_x4(qfrag[kk][f], sb + AQ + SWZ(wm * 32 + f * 16 + arow_l, kk * 32 + achk));
        }

        // ---- phase 1: s = q x k^T (Q frags in regs) ----
        float sacc[2][4][4];
        #pragma unroll
        for (int f = 0; f < 2; f++)
            #pragma unroll
            for (int j = 0; j < 4; j++)
                #pragma unroll
                for (int e = 0; e < 4; e++) sacc[f][j][e] = 0.f;
        #pragma unroll
        for (int kk = 0; kk < 4; kk++) {
            #pragma unroll
            for (int g = 0; g < 2; g++) {
                uint32_t b4[4];
                ldm_x4(b4, sK + SWZ(wn * 32 + g * 16 + brow_l, kk * 32 + bchk));
                #pragma unroll
                for (int f = 0; f < 2; f++) {
                    mma16816(sacc[f][g * 2 + 0], qfrag[kk][f], b4 + 0);
                    mma16816(sacc[f][g * 2 + 1], qfrag[kk][f], b4 + 2);
                }
            }
        }
        // quantize s -> 2 limb planes, packed u32 stores
        #pragma unroll
        for (int f = 0; f < 2; f++)
            #pragma unroll
            for (int j = 0; j < 4; j++)
                #pragma unroll
                for (int rs = 0; rs < 2; rs++) {
                    int row = wm * 32 + f * 16 + qr + rs * 8;
                    int colb = (wn * 32 + j * 8 + qc) * 2;
                    float s0 = qround8(sacc[f][j][rs * 2 + 0]);
                    float s1 = qround8(sacc[f][j][rs * 2 + 1]);
                    __half h0 = __float2half_rn(s0);
                    __half h1 = __float2half_rn(s1);
                    __half l0 = __float2half_rn(s0 - __half2float(h0));
                    __half l1 = __float2half_rn(s1 - __half2float(h1));
                    *(uint32_t*)(smem + ASH + SWZ(row, colb)) = packu32(h0, h1);
                    *(uint32_t*)(smem + ASL + SWZ(row, colb)) = packu32(l0, l1);
                }
        __syncthreads();

        // ---- phase 2: z += s x v; V frags shared across both s-limb planes ----
        #pragma unroll
        for (int kk = 0; kk < 4; kk++) {
            uint32_t bv[2][4];
            #pragma unroll
            for (int g = 0; g < 2; g++)
                ldm_x4(bv[g], sV + SWZ(wn * 32 + g * 16 + brow_l, kk * 32 + bchk));
            #pragma unroll
            for (int plane = 0; plane < 2; plane++) {
                uint32_t sp = sb + (plane ? ASL : ASH);
                uint32_t a[2][4];
                #pragma unroll
                for (int f = 0; f < 2; f++)
                    ldm_x4(a[f], sp + SWZ(wm * 32 + f * 16 + arow_l, kk * 32 + achk));
                #pragma unroll
                for (int g = 0; g < 2; g++)
                    #pragma unroll
                    for (int f = 0; f < 2; f++) {
                        mma16816(zacc[f][g * 2 + 0], a[f], bv[g] + 0);
                        mma16816(zacc[f][g * 2 + 1], a[f], bv[g] + 2);
                    }
            }
        }
    }

    // epilogue: quantize z (clamped), limb-split, interleaved layout for proj
    const int b = bh / H_, h = bh - b * H_;
    #pragma unroll
    for (int f = 0; f < 2; f++)
        #pragma unroll
        for (int j = 0; j < 4; j++)
            #pragma unroll
            for (int rs = 0; rs < 2; rs++)
                #pragma unroll
                for (int cs = 0; cs < 2; cs++) {
                    int n = q0 + wm * 32 + f * 16 + qr + rs * 8;
                    int e = wn * 32 + j * 8 + qc + cs;
                    float zq = q16_8c(zacc[f][j][rs * 2 + cs]);
                    __half hh = __float2half_rn(zq);
                    __half ll = __float2half_rn(zq - __half2float(hh));
                    g_zl[((long)(b * N_ + n)) * KH2 + h * DH_ + e] = packu32(hh, ll);
                }
}

// ---------------- launch ----------------
extern "C" void kernel_launch(void* const* d_in, const int* in_sizes, int n_in,
                              void* d_out, int out_size) {
    const float* q_in = (const float*)d_in[0];
    const float* wqkv = (const float*)d_in[1];
    const float* bqkv = (const float*)d_in[2];
    const float* wp   = (const float*)d_in[3];
    const float* bp   = (const float*)d_in[4];
    float* out = (float*)d_out;

    const long total4 = ((long)M1 * DIM_ + (long)NC1 * DIM_ + (long)DIM_ * DIM_ + NC1 + DIM_) / 4;
    prep_kernel<<<(unsigned)((total4 + 255) / 256), 256>>>(q_in, wqkv, bqkv, wp, bp);

    const int gemm_smem = 3 * GSTG;   // 98304 -> 2 CTA/SM
    cudaFuncSetAttribute(gemm_qkv_tc, cudaFuncAttributeMaxDynamicSharedMemorySize, gemm_smem);
    gemm_qkv_tc<<<dim3(NC1 / 128, M1 / 128), 256, gemm_smem>>>();       // (18, 32)

    cudaFuncSetAttribute(attn_tc_kernel, cudaFuncAttributeMaxDynamicSharedMemorySize, ATTN_SMEM);
    attn_tc_kernel<<<dim3(N_ / 128, B_ * H_), 256, ATTN_SMEM>>>();      // (16, 24)

    const int proj_smem = 4 * PSTG;   // 98304 -> 2 CTA/SM
    cudaFuncSetAttribute(gemm_proj_tc, cudaFuncAttributeMaxDynamicSharedMemorySize, proj_smem);
    gemm_proj_tc<<<dim3(DIM_ / 128, M1 / 64), 256, proj_smem>>>(out);   // (6, 64)
}

// round 16
// speedup vs baseline: 1.0846x; 1.0256x over previous
#include <cuda_runtime.h>
#include <cuda_fp16.h>
#include <cstdint>

#define B_   2
#define N_   2048
#define DIM_ 768
#define H_   12
#define DH_  64
#define M1   (B_*N_)     // 4096
#define NC1  (3*DIM_)    // 2304
#define PITCHH 1536      // bytes per half-plane row (768 halves)

// ---------------- device globals ----------------
__device__ __half g_xh[(long)M1*DIM_];       // x hi-limb plane [4096][768]
__device__ __half g_xlo[(long)M1*DIM_];      // x lo-limb plane
__device__ __half g_wq[(long)NC1*DIM_];      // wqkv single copy [2304][768]
__device__ __half g_wp[(long)DIM_*DIM_];     // wp single copy
__device__ __half g_zh[(long)M1*DIM_];       // z hi-limb plane (attention out)
__device__ __half g_zlo[(long)M1*DIM_];      // z lo-limb plane
__device__ __half g_qh[(long)B_*H_*N_*DH_];  // q single-limb [bh][n][64]
__device__ __half g_kh[(long)B_*H_*N_*DH_];  // k single-limb [bh][m][64]
__device__ __half g_vt[(long)B_*H_*DH_*N_];  // v^T single-limb [bh][e][m]
__device__ float  g_bq[NC1];
__device__ float  g_bp2[DIM_];

// ---------------- quantizers ----------------
__device__ __forceinline__ float qround8(float x) {        // round-half-even to 2^-8
    float t = __fmaf_rn(x, 256.f, 12582912.f);
    return (t - 12582912.f) * 0.00390625f;
}
__device__ __forceinline__ float q16_8c(float x) {         // with clamp (z saturates)
    float t = __fmaf_rn(x, 256.f, 12582912.f);
    float y = t - 12582912.f;
    y = fminf(fmaxf(y, -32768.f), 32767.f);
    return y * 0.00390625f;
}
__device__ __forceinline__ float q32_16(float x) {
    float t = __fmaf_rn(x, 65536.f, 12582912.f);
    return (t - 12582912.f) * 1.52587890625e-5f;
}
__device__ __forceinline__ uint32_t packu32(__half a, __half b) {
    __half2 t = __halves2half2(a, b);
    return *(uint32_t*)&t;
}
__device__ __forceinline__ uint16_t hbits(__half h) { return *(uint16_t*)&h; }

// ---------------- PTX helpers ----------------
__device__ __forceinline__ uint32_t smem_u32(const void* p) {
    uint32_t a;
    asm("{ .reg .u64 t; cvta.to.shared.u64 t, %1; cvt.u32.u64 %0, t; }" : "=r"(a) : "l"(p));
    return a;
}
#define CP_ASYNC16(dst, src) \
    asm volatile("cp.async.cg.shared.global [%0], [%1], 16;" :: "r"(dst), "l"(src) : "memory")
#define CP_COMMIT() asm volatile("cp.async.commit_group;" ::: "memory")
#define CP_WAIT(n)  asm volatile("cp.async.wait_group %0;" :: "n"(n) : "memory")

__device__ __forceinline__ void ldm_x4(uint32_t* r, uint32_t addr) {
    asm volatile("ldmatrix.sync.aligned.m8n8.x4.shared.b16 {%0,%1,%2,%3}, [%4];"
        : "=r"(r[0]), "=r"(r[1]), "=r"(r[2]), "=r"(r[3]) : "r"(addr));
}
__device__ __forceinline__ void mma16816(float* d, const uint32_t* a, const uint32_t* b) {
    asm volatile("mma.sync.aligned.m16n8k16.row.col.f32.f16.f16.f32 "
        "{%0,%1,%2,%3}, {%4,%5,%6,%7}, {%8,%9}, {%0,%1,%2,%3};"
        : "+f"(d[0]), "+f"(d[1]), "+f"(d[2]), "+f"(d[3])
        : "r"(a[0]), "r"(a[1]), "r"(a[2]), "r"(a[3]), "r"(b[0]), "r"(b[1]));
}

// 128B-pitch swizzle: XOR 16B-chunk id with row%8
#define SWZ(row, colb) ((uint32_t)((row)*128 + ((colb) ^ (((row)&7)<<4))))

// ---------------- kernel 1: vectorized quantize + plane-split ----------------
__global__ void prep_kernel(const float* __restrict__ x, const float* __restrict__ wqkv,
                            const float* __restrict__ bqkv, const float* __restrict__ wp,
                            const float* __restrict__ bp) {
    long i = (long)blockIdx.x * blockDim.x + threadIdx.x;
    const long NX4 = (long)M1 * DIM_ / 4;
    const long NW4 = (long)NC1 * DIM_ / 4;
    const long NP4 = (long)DIM_ * DIM_ / 4;
    if (i < NX4) {
        float4 v = ((const float4*)x)[i];
        __half h0, h1, h2, h3, l0, l1, l2, l3;
        float q0 = q32_16(v.x), q1 = q32_16(v.y), q2 = q32_16(v.z), q3 = q32_16(v.w);
        h0 = __float2half_rn(q0); l0 = __float2half_rn(q0 - __half2float(h0));
        h1 = __float2half_rn(q1); l1 = __float2half_rn(q1 - __half2float(h1));
        h2 = __float2half_rn(q2); l2 = __float2half_rn(q2 - __half2float(h2));
        h3 = __float2half_rn(q3); l3 = __float2half_rn(q3 - __half2float(h3));
        uint2 oh = { packu32(h0, h1), packu32(h2, h3) };
        uint2 ol = { packu32(l0, l1), packu32(l2, l3) };
        ((uint2*)g_xh)[i] = oh;
        ((uint2*)g_xlo)[i] = ol;
        return;
    }
    i -= NX4;
    if (i < NW4) {
        float4 v = ((const float4*)wqkv)[i];
        uint2 o = { packu32(__float2half_rn(qround8(v.x)), __float2half_rn(qround8(v.y))),
                    packu32(__float2half_rn(qround8(v.z)), __float2half_rn(qround8(v.w))) };
        ((uint2*)g_wq)[i] = o;
        return;
    }
    i -= NW4;
    if (i < NP4) {
        float4 v = ((const float4*)wp)[i];
        uint2 o = { packu32(__float2half_rn(qround8(v.x)), __float2half_rn(qround8(v.y))),
                    packu32(__float2half_rn(qround8(v.z)), __float2half_rn(qround8(v.w))) };
        ((uint2*)g_wp)[i] = o;
        return;
    }
    i -= NP4;
    if (i < NC1 / 4) {
        float4 v = ((const float4*)bqkv)[i];
        float4 o;
        o.x = qround8(v.x); o.y = qround8(v.y); o.z = qround8(v.z); o.w = qround8(v.w);
        ((float4*)g_bq)[i] = o;
        return;
    }
    i -= NC1 / 4;
    if (i < DIM_ / 4) {
        float4 v = ((const float4*)bp)[i];
        float4 o;
        o.x = qround8(v.x); o.y = qround8(v.y); o.z = qround8(v.z); o.w = qround8(v.w);
        ((float4*)g_bp2)[i] = o;
    }
}

// ---------------- kernel 2: QKV GEMM — A planes x single B, 2-stage, 12 chunks ----------------
// stage: Ah 16K @0 | Al 16K @16K | B 16K @32K  = 48KB; 2 stages = 96KB -> 2 CTA/SM
#define QSTG 49152

__device__ __forceinline__ void qkv_issue(uint32_t st, const char* Ah, const char* Al,
                                          const char* Bb, int kbyte, int tid) {
    #pragma unroll
    for (int i = 0; i < 4; i++) {
        int idx = tid + i * 256;
        int row = idx >> 3, c16 = (idx & 7) << 4;
        CP_ASYNC16(st + SWZ(row, c16), Ah + (long)row * PITCHH + kbyte + c16);
    }
    #pragma unroll
    for (int i = 0; i < 4; i++) {
        int idx = tid + i * 256;
        int row = idx >> 3, c16 = (idx & 7) << 4;
        CP_ASYNC16(st + 16384 + SWZ(row, c16), Al + (long)row * PITCHH + kbyte + c16);
    }
    #pragma unroll
    for (int i = 0; i < 4; i++) {
        int idx = tid + i * 256;
        int row = idx >> 3, c16 = (idx & 7) << 4;
        CP_ASYNC16(st + 32768 + SWZ(row, c16), Bb + (long)row * PITCHH + kbyte + c16);
    }
    CP_COMMIT();
}

__global__ void __launch_bounds__(256, 2) gemm_qkv_tc() {
    extern __shared__ char smem[];
    const uint32_t sb = smem_u32(smem);
    const int tid = threadIdx.x, lane = tid & 31, wid = tid >> 5;
    const int wm = wid & 3, wn = wid >> 2;   // warp tile 32m x 64n
    const int m0 = blockIdx.y * 128;
    const int n0 = blockIdx.x * 128;
    const char* Ah = (const char*)g_xh + (long)m0 * PITCHH;
    const char* Al = (const char*)g_xlo + (long)m0 * PITCHH;
    const char* Bb = (const char*)g_wq + (long)n0 * PITCHH;

    const int arow_l = (lane & 7) + ((lane >> 3) & 1) * 8;
    const int achk   = (lane >> 4) * 16;
    const int brow_l = (lane & 7) + (lane >> 4) * 8;
    const int bchk   = ((lane >> 3) & 1) * 16;

    float acc[2][8][4];
    #pragma unroll
    for (int f = 0; f < 2; f++)
        #pragma unroll
        for (int j = 0; j < 8; j++)
            #pragma unroll
            for (int e = 0; e < 4; e++) acc[f][j][e] = 0.f;

    qkv_issue(sb, Ah, Al, Bb, 0, tid);
    #pragma unroll 1
    for (int g = 0; g < 12; g++) {
        CP_WAIT(0);
        __syncthreads();   // stage g ready; all warps done reading buf (g+1)&1's old data
        if (g + 1 < 12)
            qkv_issue(sb + (uint32_t)((g + 1) & 1) * QSTG, Ah, Al, Bb, (g + 1) * 128, tid);
        uint32_t st = sb + (uint32_t)(g & 1) * QSTG;
        #pragma unroll
        for (int kk = 0; kk < 4; kk++) {
            uint32_t ah[2][4], al[2][4];
            #pragma unroll
            for (int f = 0; f < 2; f++) {
                ldm_x4(ah[f], st + SWZ(wm * 32 + f * 16 + arow_l, kk * 32 + achk));
                ldm_x4(al[f], st + 16384 + SWZ(wm * 32 + f * 16 + arow_l, kk * 32 + achk));
            }
            #pragma unroll
            for (int gg = 0; gg < 4; gg++) {
                uint32_t b4[4];
                ldm_x4(b4, st + 32768 + SWZ(wn * 64 + gg * 16 + brow_l, kk * 32 + bchk));
                #pragma unroll
                for (int f = 0; f < 2; f++) {
                    mma16816(acc[f][gg * 2 + 0], ah[f], b4 + 0);
                    mma16816(acc[f][gg * 2 + 1], ah[f], b4 + 2);
                    mma16816(acc[f][gg * 2 + 0], al[f], b4 + 0);
                    mma16816(acc[f][gg * 2 + 1], al[f], b4 + 2);
                }
            }
        }
    }

    // epilogue: bias + (16,8) quant -> single-limb q/k/v layouts
    const int rb = m0 + wm * 32 + (lane >> 2);
    const int cb = n0 + wn * 64 + (lane & 3) * 2;
    #pragma unroll
    for (int f = 0; f < 2; f++) {
        #pragma unroll
        for (int j = 0; j < 8; j++) {
            int nb = cb + j * 8;                 // even
            float b0 = g_bq[nb], b1 = g_bq[nb + 1];
            int h = nb / 192;
            int rr = nb - h * 192;
            int seg = rr >> 6, e = rr & 63;      // e even
            #pragma unroll
            for (int rs = 0; rs < 2; rs++) {
                int m = rb + f * 16 + rs * 8;
                int bi = m >> 11, nr = m & 2047;
                long bh = bi * H_ + h;
                __half h0 = __float2half_rn(qround8(acc[f][j][rs * 2 + 0] + b0));
                __half h1 = __float2half_rn(qround8(acc[f][j][rs * 2 + 1] + b1));
                if (seg == 0) {
                    *(uint32_t*)(g_qh + (bh * N_ + nr) * DH_ + e) = packu32(h0, h1);
                } else if (seg == 1) {
                    *(uint32_t*)(g_kh + (bh * N_ + nr) * DH_ + e) = packu32(h0, h1);
                } else {
                    g_vt[(bh * DH_ + e) * N_ + nr] = h0;
                    g_vt[(bh * DH_ + e + 1) * N_ + nr] = h1;
                }
            }
        }
    }
}

// ---------------- kernel 4: output projection — z planes x single wp, 3-stage ----------------
// stage: Ah 8K @0 | Al 8K @8K | B 16K @16K = 32KB; 3 stages = 96KB -> 2 CTA/SM
#define PSTG 32768

__device__ __forceinline__ void proj_issue(uint32_t st, const char* Ah, const char* Al,
                                           const char* Bb, int kbyte, int tid) {
    #pragma unroll
    for (int i = 0; i < 2; i++) {
        int idx = tid + i * 256;
        int row = idx >> 3, c16 = (idx & 7) << 4;
        CP_ASYNC16(st + SWZ(row, c16), Ah + (long)row * PITCHH + kbyte + c16);
    }
    #pragma unroll
    for (int i = 0; i < 2; i++) {
        int idx = tid + i * 256;
        int row = idx >> 3, c16 = (idx & 7) << 4;
        CP_ASYNC16(st + 8192 + SWZ(row, c16), Al + (long)row * PITCHH + kbyte + c16);
    }
    #pragma unroll
    for (int i = 0; i < 4; i++) {
        int idx = tid + i * 256;
        int row = idx >> 3, c16 = (idx & 7) << 4;
        CP_ASYNC16(st + 16384 + SWZ(row, c16), Bb + (long)row * PITCHH + kbyte + c16);
    }
    CP_COMMIT();
}

__global__ void __launch_bounds__(256, 2) gemm_proj_tc(float* __restrict__ out) {
    extern __shared__ char smem[];
    const uint32_t sb = smem_u32(smem);
    const int tid = threadIdx.x, lane = tid & 31, wid = tid >> 5;
    const int wm = wid & 1, wn = wid >> 1;       // warp tile 32m x 32n
    const int m0 = blockIdx.y * 64;
    const int n0 = blockIdx.x * 128;
    const char* Ah = (const char*)g_zh + (long)m0 * PITCHH;
    const char* Al = (const char*)g_zlo + (long)m0 * PITCHH;
    const char* Bb = (const char*)g_wp + (long)n0 * PITCHH;

    const int arow_l = (lane & 7) + ((lane >> 3) & 1) * 8;
    const int achk   = (lane >> 4) * 16;
    const int brow_l = (lane & 7) + (lane >> 4) * 8;
    const int bchk   = ((lane >> 3) & 1) * 16;

    float acc[2][4][4];
    #pragma unroll
    for (int f = 0; f < 2; f++)
        #pragma unroll
        for (int j = 0; j < 4; j++)
            #pragma unroll
            for (int e = 0; e < 4; e++) acc[f][j][e] = 0.f;

    proj_issue(sb + 0 * PSTG, Ah, Al, Bb, 0, tid);
    proj_issue(sb + 1 * PSTG, Ah, Al, Bb, 128, tid);
    #pragma unroll 1
    for (int g = 0; g < 12; g++) {
        if (g + 2 < 12) { CP_WAIT(1); } else { CP_WAIT(0); }
        __syncthreads();
        if (g + 2 < 12)
            proj_issue(sb + (uint32_t)((g + 2) % 3) * PSTG, Ah, Al, Bb, (g + 2) * 128, tid);
        uint32_t st = sb + (uint32_t)(g % 3) * PSTG;
        #pragma unroll
        for (int kk = 0; kk < 4; kk++) {
            uint32_t ah[2][4], al[2][4];
            #pragma unroll
            for (int f = 0; f < 2; f++) {
                ldm_x4(ah[f], st + SWZ(wm * 32 + f * 16 + arow_l, kk * 32 + achk));
                ldm_x4(al[f], st + 8192 + SWZ(wm * 32 + f * 16 + arow_l, kk * 32 + achk));
            }
            #pragma unroll
            for (int gg = 0; gg < 2; gg++) {
                uint32_t b4[4];
                ldm_x4(b4, st + 16384 + SWZ(wn * 32 + gg * 16 + brow_l, kk * 32 + bchk));
                #pragma unroll
                for (int f = 0; f < 2; f++) {
                    mma16816(acc[f][gg * 2 + 0], ah[f], b4 + 0);
                    mma16816(acc[f][gg * 2 + 1], ah[f], b4 + 2);
                    mma16816(acc[f][gg * 2 + 0], al[f], b4 + 0);
                    mma16816(acc[f][gg * 2 + 1], al[f], b4 + 2);
                }
            }
        }
    }

    const int rb = m0 + wm * 32 + (lane >> 2);
    const int cb = n0 + wn * 32 + (lane & 3) * 2;
    #pragma unroll
    for (int f = 0; f < 2; f++)
        #pragma unroll
        for (int j = 0; j < 4; j++)
            #pragma unroll
            for (int cs = 0; cs < 2; cs++) {
                int n = cb + j * 8 + cs;
                float bias = g_bp2[n];
                #pragma unroll
                for (int rs = 0; rs < 2; rs++) {
                    int m = rb + f * 16 + rs * 8;
                    out[(long)m * DIM_ + n] = qround8(acc[f][j][rs * 2 + cs] + bias);
                }
            }
}

// ---------------- kernel 3: flash attention, 4-stage KV ring (plane z epilogue) ----------------
// smem: Q 16K | KV 4 stages x (K 8K + V 8K) = 64K | Sh 16K | Sl 16K  = 112KB (2 CTA/SM)
#define AQ    0u
#define AKV   16384u
#define ASTG  16384u
#define ASH   81920u
#define ASL   98304u
#define ATTN_SMEM 114688

__device__ __forceinline__ void attn_issue(uint32_t stage_base,
        const char* khb, const char* vtb, int kb, int tid) {
    #pragma unroll
    for (int i = 0; i < 2; i++) {
        int idx = tid + i * 256;
        int row = idx >> 3, c16 = (idx & 7) << 4;
        CP_ASYNC16(stage_base + SWZ(row, c16), khb + (long)(kb + row) * 128 + c16);
    }
    #pragma unroll
    for (int i = 0; i < 2; i++) {
        int idx = tid + i * 256;
        int row = idx >> 3, c16 = (idx & 7) << 4;
        CP_ASYNC16(stage_base + 8192 + SWZ(row, c16), vtb + (long)row * (N_ * 2) + kb * 2 + c16);
    }
    CP_COMMIT();
}

__global__ void __launch_bounds__(256, 2) attn_tc_kernel() {
    extern __shared__ char smem[];
    const uint32_t sb = smem_u32(smem);
    const int tid = threadIdx.x;
    const int lane = tid & 31, wid = tid >> 5;
    const int wm = wid & 3, wn = wid >> 2;
    const int bh = blockIdx.y;
    const int q0 = blockIdx.x * 128;

    const char* qhb = (const char*)(g_qh + ((long)bh * N_ + q0) * DH_);
    const char* khb = (const char*)(g_kh + (long)bh * N_ * DH_);
    const char* vtb = (const char*)(g_vt + (long)bh * DH_ * N_);

    #pragma unroll
    for (int i = 0; i < 4; i++) {
        int idx = tid + i * 256;
        int row = idx >> 3, c16 = (idx & 7) << 4;
        CP_ASYNC16(sb + AQ + SWZ(row, c16), qhb + (long)row * 128 + c16);
    }
    attn_issue(sb + AKV + 0 * ASTG, khb, vtb, 0, tid);
    attn_issue(sb + AKV + 1 * ASTG, khb, vtb, 64, tid);
    attn_issue(sb + AKV + 2 * ASTG, khb, vtb, 128, tid);

    const int arow_l = (lane & 7) + ((lane >> 3) & 1) * 8;
    const int achk   = (lane >> 4) * 16;
    const int brow_l = (lane & 7) + (lane >> 4) * 8;
    const int bchk   = ((lane >> 3) & 1) * 16;
    const int qr     = lane >> 2;
    const int qc     = (lane & 3) * 2;

    uint32_t qfrag[4][2][4];
    float zacc[2][4][4];
    #pragma unroll
    for (int f = 0; f < 2; f++)
        #pragma unroll
        for (int j = 0; j < 4; j++)
            #pragma unroll
            for (int e = 0; e < 4; e++) zacc[f][j][e] = 0.f;

    #pragma unroll 1
    for (int it = 0; it < 32; it++) {
        if (it + 3 < 32) { CP_WAIT(2); } else { CP_WAIT(0); }
        __syncthreads();
        if (it + 3 < 32)
            attn_issue(sb + AKV + (uint32_t)((it + 3) & 3) * ASTG, khb, vtb, (it + 3) * 64, tid);
        const uint32_t sK = sb + AKV + (uint32_t)(it & 3) * ASTG;
        const uint32_t sV = sK + 8192u;

        if (it == 0) {
            #pragma unroll
            for (int kk = 0; kk < 4; kk++)
                #pragma unroll
                for (int f = 0; f < 2; f++)
                    ldm_x4(qfrag[kk][f], sb + AQ + SWZ(wm * 32 + f * 16 + arow_l, kk * 32 + achk));
        }

        // phase 1: s = q x k^T
        float sacc[2][4][4];
        #pragma unroll
        for (int f = 0; f < 2; f++)
            #pragma unroll
            for (int j = 0; j < 4; j++)
                #pragma unroll
                for (int e = 0; e < 4; e++) sacc[f][j][e] = 0.f;
        #pragma unroll
        for (int kk = 0; kk < 4; kk++) {
            #pragma unroll
            for (int g = 0; g < 2; g++) {
                uint32_t b4[4];
                ldm_x4(b4, sK + SWZ(wn * 32 + g * 16 + brow_l, kk * 32 + bchk));
                #pragma unroll
                for (int f = 0; f < 2; f++) {
                    mma16816(sacc[f][g * 2 + 0], qfrag[kk][f], b4 + 0);
                    mma16816(sacc[f][g * 2 + 1], qfrag[kk][f], b4 + 2);
                }
            }
        }
        // quantize s -> 2 limb planes, packed u32 stores
        #pragma unroll
        for (int f = 0; f < 2; f++)
            #pragma unroll
            for (int j = 0; j < 4; j++)
                #pragma unroll
                for (int rs = 0; rs < 2; rs++) {
                    int row = wm * 32 + f * 16 + qr + rs * 8;
                    int colb = (wn * 32 + j * 8 + qc) * 2;
                    float s0 = qround8(sacc[f][j][rs * 2 + 0]);
                    float s1 = qround8(sacc[f][j][rs * 2 + 1]);
                    __half h0 = __float2half_rn(s0);
                    __half h1 = __float2half_rn(s1);
                    __half l0 = __float2half_rn(s0 - __half2float(h0));
                    __half l1 = __float2half_rn(s1 - __half2float(h1));
                    *(uint32_t*)(smem + ASH + SWZ(row, colb)) = packu32(h0, h1);
                    *(uint32_t*)(smem + ASL + SWZ(row, colb)) = packu32(l0, l1);
                }
        __syncthreads();

        // phase 2: z += s x v; V frags shared across both s-limb planes
        #pragma unroll
        for (int kk = 0; kk < 4; kk++) {
            uint32_t bv[2][4];
            #pragma unroll
            for (int g = 0; g < 2; g++)
                ldm_x4(bv[g], sV + SWZ(wn * 32 + g * 16 + brow_l, kk * 32 + bchk));
            #pragma unroll
            for (int plane = 0; plane < 2; plane++) {
                uint32_t sp = sb + (plane ? ASL : ASH);
                uint32_t a[2][4];
                #pragma unroll
                for (int f = 0; f < 2; f++)
                    ldm_x4(a[f], sp + SWZ(wm * 32 + f * 16 + arow_l, kk * 32 + achk));
                #pragma unroll
                for (int g = 0; g < 2; g++)
                    #pragma unroll
                    for (int f = 0; f < 2; f++) {
                        mma16816(zacc[f][g * 2 + 0], a[f], bv[g] + 0);
                        mma16816(zacc[f][g * 2 + 1], a[f], bv[g] + 2);
                    }
            }
        }
    }

    // epilogue: quantize z (clamped), write hi/lo planes for proj
    const int b = bh / H_, h = bh - b * H_;
    #pragma unroll
    for (int f = 0; f < 2; f++)
        #pragma unroll
        for (int j = 0; j < 4; j++)
            #pragma unroll
            for (int rs = 0; rs < 2; rs++) {
                int n = q0 + wm * 32 + f * 16 + qr + rs * 8;
                int e = wn * 32 + j * 8 + qc;   // even
                float z0 = q16_8c(zacc[f][j][rs * 2 + 0]);
                float z1 = q16_8c(zacc[f][j][rs * 2 + 1]);
                __half h0 = __float2half_rn(z0);
                __half h1 = __float2half_rn(z1);
                __half l0 = __float2half_rn(z0 - __half2float(h0));
                __half l1 = __float2half_rn(z1 - __half2float(h1));
                long off = (long)(b * N_ + n) * DIM_ + h * DH_ + e;
                *(uint32_t*)(g_zh + off)  = packu32(h0, h1);
                *(uint32_t*)(g_zlo + off) = packu32(l0, l1);
            }
}

// ---------------- launch ----------------
extern "C" void kernel_launch(void* const* d_in, const int* in_sizes, int n_in,
                              void* d_out, int out_size) {
    const float* q_in = (const float*)d_in[0];
    const float* wqkv = (const float*)d_in[1];
    const float* bqkv = (const float*)d_in[2];
    const float* wp   = (const float*)d_in[3];
    const float* bp   = (const float*)d_in[4];
    float* out = (float*)d_out;

    const long total4 = ((long)M1 * DIM_ + (long)NC1 * DIM_ + (long)DIM_ * DIM_ + NC1 + DIM_) / 4;
    prep_kernel<<<(unsigned)((total4 + 255) / 256), 256>>>(q_in, wqkv, bqkv, wp, bp);

    const int qkv_smem = 2 * QSTG;   // 98304 -> 2 CTA/SM
    cudaFuncSetAttribute(gemm_qkv_tc, cudaFuncAttributeMaxDynamicSharedMemorySize, qkv_smem);
    gemm_qkv_tc<<<dim3(NC1 / 128, M1 / 128), 256, qkv_smem>>>();        // (18, 32)

    cudaFuncSetAttribute(attn_tc_kernel, cudaFuncAttributeMaxDynamicSharedMemorySize, ATTN_SMEM);
    attn_tc_kernel<<<dim3(N_ / 128, B_ * H_), 256, ATTN_SMEM>>>();      // (16, 24)

    const int proj_smem = 3 * PSTG;   // 98304 -> 2 CTA/SM
    cudaFuncSetAttribute(gemm_proj_tc, cudaFuncAttributeMaxDynamicSharedMemorySize, proj_smem);
    gemm_proj_tc<<<dim3(DIM_ / 128, M1 / 64), 256, proj_smem>>>(out);   // (6, 64)
}

// round 17
// speedup vs baseline: 1.0931x; 1.0078x over previous
#include <cuda_runtime.h>
#include <cuda_fp16.h>
#include <cstdint>

#define B_   2
#define N_   2048
#define DIM_ 768
#define H_   12
#define DH_  64
#define M1   (B_*N_)     // 4096
#define NC1  (3*DIM_)    // 2304
#define PITCHH 1536      // bytes per half-plane row (768 halves)

// ---------------- device globals ----------------
__device__ __half g_xh[(long)M1*DIM_];       // x hi-limb plane [4096][768]
__device__ __half g_xlo[(long)M1*DIM_];      // x lo-limb plane
__device__ __half g_wq[(long)NC1*DIM_];      // wqkv single copy [2304][768]
__device__ __half g_wp[(long)DIM_*DIM_];     // wp single copy
__device__ __half g_zh[(long)M1*DIM_];       // z hi-limb plane (attention out)
__device__ __half g_zlo[(long)M1*DIM_];      // z lo-limb plane
__device__ __half g_qh[(long)B_*H_*N_*DH_];  // q single-limb [bh][n][64]
__device__ __half g_kh[(long)B_*H_*N_*DH_];  // k single-limb [bh][m][64]
__device__ __half g_vt[(long)B_*H_*DH_*N_];  // v^T single-limb [bh][e][m]
__device__ float  g_bq[NC1];
__device__ float  g_bp2[DIM_];

// ---------------- quantizers ----------------
__device__ __forceinline__ float qround8(float x) {        // round-half-even to 2^-8
    float t = __fmaf_rn(x, 256.f, 12582912.f);
    return (t - 12582912.f) * 0.00390625f;
}
__device__ __forceinline__ float q16_8c(float x) {         // with clamp (z saturates)
    float t = __fmaf_rn(x, 256.f, 12582912.f);
    float y = t - 12582912.f;
    y = fminf(fmaxf(y, -32768.f), 32767.f);
    return y * 0.00390625f;
}
__device__ __forceinline__ float q32_16(float x) {
    float t = __fmaf_rn(x, 65536.f, 12582912.f);
    return (t - 12582912.f) * 1.52587890625e-5f;
}
__device__ __forceinline__ uint32_t packu32(__half a, __half b) {
    __half2 t = __halves2half2(a, b);
    return *(uint32_t*)&t;
}

// ---------------- PTX helpers ----------------
__device__ __forceinline__ uint32_t smem_u32(const void* p) {
    uint32_t a;
    asm("{ .reg .u64 t; cvta.to.shared.u64 t, %1; cvt.u32.u64 %0, t; }" : "=r"(a) : "l"(p));
    return a;
}
#define CP_ASYNC16(dst, src) \
    asm volatile("cp.async.cg.shared.global [%0], [%1], 16;" :: "r"(dst), "l"(src) : "memory")
#define CP_COMMIT() asm volatile("cp.async.commit_group;" ::: "memory")
#define CP_WAIT(n)  asm volatile("cp.async.wait_group %0;" :: "n"(n) : "memory")

__device__ __forceinline__ void ldm_x4(uint32_t* r, uint32_t addr) {
    asm volatile("ldmatrix.sync.aligned.m8n8.x4.shared.b16 {%0,%1,%2,%3}, [%4];"
        : "=r"(r[0]), "=r"(r[1]), "=r"(r[2]), "=r"(r[3]) : "r"(addr));
}
// NOTE: non-volatile — mma.sync is register-only; letting ptxas reschedule it is
// the whole point (software pipelining of LDSM latency + accumulator RAW gaps).
__device__ __forceinline__ void mma16816(float* d, const uint32_t* a, const uint32_t* b) {
    asm("mma.sync.aligned.m16n8k16.row.col.f32.f16.f16.f32 "
        "{%0,%1,%2,%3}, {%4,%5,%6,%7}, {%8,%9}, {%0,%1,%2,%3};"
        : "+f"(d[0]), "+f"(d[1]), "+f"(d[2]), "+f"(d[3])
        : "r"(a[0]), "r"(a[1]), "r"(a[2]), "r"(a[3]), "r"(b[0]), "r"(b[1]));
}

// 128B-pitch swizzle: XOR 16B-chunk id with row%8
#define SWZ(row, colb) ((uint32_t)((row)*128 + ((colb) ^ (((row)&7)<<4))))

// ---------------- kernel 1: vectorized quantize + plane-split ----------------
__global__ void prep_kernel(const float* __restrict__ x, const float* __restrict__ wqkv,
                            const float* __restrict__ bqkv, const float* __restrict__ wp,
                            const float* __restrict__ bp) {
    long i = (long)blockIdx.x * blockDim.x + threadIdx.x;
    const long NX4 = (long)M1 * DIM_ / 4;
    const long NW4 = (long)NC1 * DIM_ / 4;
    const long NP4 = (long)DIM_ * DIM_ / 4;
    if (i < NX4) {
        float4 v = ((const float4*)x)[i];
        __half h0, h1, h2, h3, l0, l1, l2, l3;
        float q0 = q32_16(v.x), q1 = q32_16(v.y), q2 = q32_16(v.z), q3 = q32_16(v.w);
        h0 = __float2half_rn(q0); l0 = __float2half_rn(q0 - __half2float(h0));
        h1 = __float2half_rn(q1); l1 = __float2half_rn(q1 - __half2float(h1));
        h2 = __float2half_rn(q2); l2 = __float2half_rn(q2 - __half2float(h2));
        h3 = __float2half_rn(q3); l3 = __float2half_rn(q3 - __half2float(h3));
        uint2 oh = { packu32(h0, h1), packu32(h2, h3) };
        uint2 ol = { packu32(l0, l1), packu32(l2, l3) };
        ((uint2*)g_xh)[i] = oh;
        ((uint2*)g_xlo)[i] = ol;
        return;
    }
    i -= NX4;
    if (i < NW4) {
        float4 v = ((const float4*)wqkv)[i];
        uint2 o = { packu32(__float2half_rn(qround8(v.x)), __float2half_rn(qround8(v.y))),
                    packu32(__float2half_rn(qround8(v.z)), __float2half_rn(qround8(v.w))) };
        ((uint2*)g_wq)[i] = o;
        return;
    }
    i -= NW4;
    if (i < NP4) {
        float4 v = ((const float4*)wp)[i];
        uint2 o = { packu32(__float2half_rn(qround8(v.x)), __float2half_rn(qround8(v.y))),
                    packu32(__float2half_rn(qround8(v.z)), __float2half_rn(qround8(v.w))) };
        ((uint2*)g_wp)[i] = o;
        return;
    }
    i -= NP4;
    if (i < NC1 / 4) {
        float4 v = ((const float4*)bqkv)[i];
        float4 o;
        o.x = qround8(v.x); o.y = qround8(v.y); o.z = qround8(v.z); o.w = qround8(v.w);
        ((float4*)g_bq)[i] = o;
        return;
    }
    i -= NC1 / 4;
    if (i < DIM_ / 4) {
        float4 v = ((const float4*)bp)[i];
        float4 o;
        o.x = qround8(v.x); o.y = qround8(v.y); o.z = qround8(v.z); o.w = qround8(v.w);
        ((float4*)g_bp2)[i] = o;
    }
}

// ---------------- kernel 2: QKV GEMM — A planes x single B, 2-stage, 12 chunks ----------------
// stage: Ah 16K @0 | Al 16K @16K | B 16K @32K  = 48KB; 2 stages = 96KB -> 2 CTA/SM
#define QSTG 49152

__device__ __forceinline__ void qkv_issue(uint32_t st, const char* Ah, const char* Al,
                                          const char* Bb, int kbyte, int tid) {
    #pragma unroll
    for (int i = 0; i < 4; i++) {
        int idx = tid + i * 256;
        int row = idx >> 3, c16 = (idx & 7) << 4;
        CP_ASYNC16(st + SWZ(row, c16), Ah + (long)row * PITCHH + kbyte + c16);
    }
    #pragma unroll
    for (int i = 0; i < 4; i++) {
        int idx = tid + i * 256;
        int row = idx >> 3, c16 = (idx & 7) << 4;
        CP_ASYNC16(st + 16384 + SWZ(row, c16), Al + (long)row * PITCHH + kbyte + c16);
    }
    #pragma unroll
    for (int i = 0; i < 4; i++) {
        int idx = tid + i * 256;
        int row = idx >> 3, c16 = (idx & 7) << 4;
        CP_ASYNC16(st + 32768 + SWZ(row, c16), Bb + (long)row * PITCHH + kbyte + c16);
    }
    CP_COMMIT();
}

__global__ void __launch_bounds__(256, 2) gemm_qkv_tc() {
    extern __shared__ char smem[];
    const uint32_t sb = smem_u32(smem);
    const int tid = threadIdx.x, lane = tid & 31, wid = tid >> 5;
    const int wm = wid & 3, wn = wid >> 2;   // warp tile 32m x 64n
    const int m0 = blockIdx.y * 128;
    const int n0 = blockIdx.x * 128;
    const char* Ah = (const char*)g_xh + (long)m0 * PITCHH;
    const char* Al = (const char*)g_xlo + (long)m0 * PITCHH;
    const char* Bb = (const char*)g_wq + (long)n0 * PITCHH;

    const int arow_l = (lane & 7) + ((lane >> 3) & 1) * 8;
    const int achk   = (lane >> 4) * 16;
    const int brow_l = (lane & 7) + (lane >> 4) * 8;
    const int bchk   = ((lane >> 3) & 1) * 16;

    float acc[2][8][4];
    #pragma unroll
    for (int f = 0; f < 2; f++)
        #pragma unroll
        for (int j = 0; j < 8; j++)
            #pragma unroll
            for (int e = 0; e < 4; e++) acc[f][j][e] = 0.f;

    qkv_issue(sb, Ah, Al, Bb, 0, tid);
    #pragma unroll 1
    for (int g = 0; g < 12; g++) {
        CP_WAIT(0);
        __syncthreads();
        if (g + 1 < 12)
            qkv_issue(sb + (uint32_t)((g + 1) & 1) * QSTG, Ah, Al, Bb, (g + 1) * 128, tid);
        uint32_t st = sb + (uint32_t)(g & 1) * QSTG;
        #pragma unroll
        for (int kk = 0; kk < 4; kk++) {
            uint32_t ah[2][4], al[2][4], b4[4][4];
            #pragma unroll
            for (int f = 0; f < 2; f++) {
                ldm_x4(ah[f], st + SWZ(wm * 32 + f * 16 + arow_l, kk * 32 + achk));
                ldm_x4(al[f], st + 16384 + SWZ(wm * 32 + f * 16 + arow_l, kk * 32 + achk));
            }
            #pragma unroll
            for (int gg = 0; gg < 4; gg++)
                ldm_x4(b4[gg], st + 32768 + SWZ(wn * 64 + gg * 16 + brow_l, kk * 32 + bchk));
            // hi-plane block: 16 independent MMAs
            #pragma unroll
            for (int gg = 0; gg < 4; gg++)
                #pragma unroll
                for (int f = 0; f < 2; f++) {
                    mma16816(acc[f][gg * 2 + 0], ah[f], b4[gg] + 0);
                    mma16816(acc[f][gg * 2 + 1], ah[f], b4[gg] + 2);
                }
            // lo-plane block: same accumulators, 16 MMAs later
            #pragma unroll
            for (int gg = 0; gg < 4; gg++)
                #pragma unroll
                for (int f = 0; f < 2; f++) {
                    mma16816(acc[f][gg * 2 + 0], al[f], b4[gg] + 0);
                    mma16816(acc[f][gg * 2 + 1], al[f], b4[gg] + 2);
                }
        }
    }

    // epilogue: bias + (16,8) quant -> single-limb q/k/v layouts
    const int rb = m0 + wm * 32 + (lane >> 2);
    const int cb = n0 + wn * 64 + (lane & 3) * 2;
    #pragma unroll
    for (int f = 0; f < 2; f++) {
        #pragma unroll
        for (int j = 0; j < 8; j++) {
            int nb = cb + j * 8;                 // even
            float b0 = g_bq[nb], b1 = g_bq[nb + 1];
            int h = nb / 192;
            int rr = nb - h * 192;
            int seg = rr >> 6, e = rr & 63;      // e even
            #pragma unroll
            for (int rs = 0; rs < 2; rs++) {
                int m = rb + f * 16 + rs * 8;
                int bi = m >> 11, nr = m & 2047;
                long bh = bi * H_ + h;
                __half h0 = __float2half_rn(qround8(acc[f][j][rs * 2 + 0] + b0));
                __half h1 = __float2half_rn(qround8(acc[f][j][rs * 2 + 1] + b1));
                if (seg == 0) {
                    *(uint32_t*)(g_qh + (bh * N_ + nr) * DH_ + e) = packu32(h0, h1);
                } else if (seg == 1) {
                    *(uint32_t*)(g_kh + (bh * N_ + nr) * DH_ + e) = packu32(h0, h1);
                } else {
                    g_vt[(bh * DH_ + e) * N_ + nr] = h0;
                    g_vt[(bh * DH_ + e + 1) * N_ + nr] = h1;
                }
            }
        }
    }
}

// ---------------- kernel 4: output projection — z planes x single wp, 3-stage ----------------
// stage: Ah 8K @0 | Al 8K @8K | B 16K @16K = 32KB; 3 stages = 96KB -> 2 CTA/SM
#define PSTG 32768

__device__ __forceinline__ void proj_issue(uint32_t st, const char* Ah, const char* Al,
                                           const char* Bb, int kbyte, int tid) {
    #pragma unroll
    for (int i = 0; i < 2; i++) {
        int idx = tid + i * 256;
        int row = idx >> 3, c16 = (idx & 7) << 4;
        CP_ASYNC16(st + SWZ(row, c16), Ah + (long)row * PITCHH + kbyte + c16);
    }
    #pragma unroll
    for (int i = 0; i < 2; i++) {
        int idx = tid + i * 256;
        int row = idx >> 3, c16 = (idx & 7) << 4;
        CP_ASYNC16(st + 8192 + SWZ(row, c16), Al + (long)row * PITCHH + kbyte + c16);
    }
    #pragma unroll
    for (int i = 0; i < 4; i++) {
        int idx = tid + i * 256;
        int row = idx >> 3, c16 = (idx & 7) << 4;
        CP_ASYNC16(st + 16384 + SWZ(row, c16), Bb + (long)row * PITCHH + kbyte + c16);
    }
    CP_COMMIT();
}

__global__ void __launch_bounds__(256, 2) gemm_proj_tc(float* __restrict__ out) {
    extern __shared__ char smem[];
    const uint32_t sb = smem_u32(smem);
    const int tid = threadIdx.x, lane = tid & 31, wid = tid >> 5;
    const int wm = wid & 1, wn = wid >> 1;       // warp tile 32m x 32n
    const int m0 = blockIdx.y * 64;
    const int n0 = blockIdx.x * 128;
    const char* Ah = (const char*)g_zh + (long)m0 * PITCHH;
    const char* Al = (const char*)g_zlo + (long)m0 * PITCHH;
    const char* Bb = (const char*)g_wp + (long)n0 * PITCHH;

    const int arow_l = (lane & 7) + ((lane >> 3) & 1) * 8;
    const int achk   = (lane >> 4) * 16;
    const int brow_l = (lane & 7) + (lane >> 4) * 8;
    const int bchk   = ((lane >> 3) & 1) * 16;

    float acc[2][4][4];
    #pragma unroll
    for (int f = 0; f < 2; f++)
        #pragma unroll
        for (int j = 0; j < 4; j++)
            #pragma unroll
            for (int e = 0; e < 4; e++) acc[f][j][e] = 0.f;

    proj_issue(sb + 0 * PSTG, Ah, Al, Bb, 0, tid);
    proj_issue(sb + 1 * PSTG, Ah, Al, Bb, 128, tid);
    #pragma unroll 1
    for (int g = 0; g < 12; g++) {
        if (g + 2 < 12) { CP_WAIT(1); } else { CP_WAIT(0); }
        __syncthreads();
        if (g + 2 < 12)
            proj_issue(sb + (uint32_t)((g + 2) % 3) * PSTG, Ah, Al, Bb, (g + 2) * 128, tid);
        uint32_t st = sb + (uint32_t)(g % 3) * PSTG;
        #pragma unroll
        for (int kk = 0; kk < 4; kk++) {
            uint32_t ah[2][4], al[2][4], b4[2][4];
            #pragma unroll
            for (int f = 0; f < 2; f++) {
                ldm_x4(ah[f], st + SWZ(wm * 32 + f * 16 + arow_l, kk * 32 + achk));
                ldm_x4(al[f], st + 8192 + SWZ(wm * 32 + f * 16 + arow_l, kk * 32 + achk));
            }
            #pragma unroll
            for (int gg = 0; gg < 2; gg++)
                ldm_x4(b4[gg], st + 16384 + SWZ(wn * 32 + gg * 16 + brow_l, kk * 32 + bchk));
            // hi-plane block (8 independent MMAs), then lo-plane block
            #pragma unroll
            for (int gg = 0; gg < 2; gg++)
                #pragma unroll
                for (int f = 0; f < 2; f++) {
                    mma16816(acc[f][gg * 2 + 0], ah[f], b4[gg] + 0);
                    mma16816(acc[f][gg * 2 + 1], ah[f], b4[gg] + 2);
                }
            #pragma unroll
            for (int gg = 0; gg < 2; gg++)
                #pragma unroll
                for (int f = 0; f < 2; f++) {
                    mma16816(acc[f][gg * 2 + 0], al[f], b4[gg] + 0);
                    mma16816(acc[f][gg * 2 + 1], al[f], b4[gg] + 2);
                }
        }
    }

    const int rb = m0 + wm * 32 + (lane >> 2);
    const int cb = n0 + wn * 32 + (lane & 3) * 2;
    #pragma unroll
    for (int f = 0; f < 2; f++)
        #pragma unroll
        for (int j = 0; j < 4; j++)
            #pragma unroll
            for (int cs = 0; cs < 2; cs++) {
                int n = cb + j * 8 + cs;
                float bias = g_bp2[n];
                #pragma unroll
                for (int rs = 0; rs < 2; rs++) {
                    int m = rb + f * 16 + rs * 8;
                    out[(long)m * DIM_ + n] = qround8(acc[f][j][rs * 2 + cs] + bias);
                }
            }
}

// ---------------- kernel 3: flash attention, 4-stage KV ring ----------------
// smem: Q 16K | KV 4 stages x (K 8K + V 8K) = 64K | Sh 16K | Sl 16K  = 112KB (2 CTA/SM)
#define AQ    0u
#define AKV   16384u
#define ASTG  16384u
#define ASH   81920u
#define ASL   98304u
#define ATTN_SMEM 114688

__device__ __forceinline__ void attn_issue(uint32_t stage_base,
        const char* khb, const char* vtb, int kb, int tid) {
    #pragma unroll
    for (int i = 0; i < 2; i++) {
        int idx = tid + i * 256;
        int row = idx >> 3, c16 = (idx & 7) << 4;
        CP_ASYNC16(stage_base + SWZ(row, c16), khb + (long)(kb + row) * 128 + c16);
    }
    #pragma unroll
    for (int i = 0; i < 2; i++) {
        int idx = tid + i * 256;
        int row = idx >> 3, c16 = (idx & 7) << 4;
        CP_ASYNC16(stage_base + 8192 + SWZ(row, c16), vtb + (long)row * (N_ * 2) + kb * 2 + c16);
    }
    CP_COMMIT();
}

__global__ void __launch_bounds__(256, 2) attn_tc_kernel() {
    extern __shared__ char smem[];
    const uint32_t sb = smem_u32(smem);
    const int tid = threadIdx.x;
    const int lane = tid & 31, wid = tid >> 5;
    const int wm = wid & 3, wn = wid >> 2;
    const int bh = blockIdx.y;
    const int q0 = blockIdx.x * 128;

    const char* qhb = (const char*)(g_qh + ((long)bh * N_ + q0) * DH_);
    const char* khb = (const char*)(g_kh + (long)bh * N_ * DH_);
    const char* vtb = (const char*)(g_vt + (long)bh * DH_ * N_);

    #pragma unroll
    for (int i = 0; i < 4; i++) {
        int idx = tid + i * 256;
        int row = idx >> 3, c16 = (idx & 7) << 4;
        CP_ASYNC16(sb + AQ + SWZ(row, c16), qhb + (long)row * 128 + c16);
    }
    attn_issue(sb + AKV + 0 * ASTG, khb, vtb, 0, tid);
    attn_issue(sb + AKV + 1 * ASTG, khb, vtb, 64, tid);
    attn_issue(sb + AKV + 2 * ASTG, khb, vtb, 128, tid);

    const int arow_l = (lane & 7) + ((lane >> 3) & 1) * 8;
    const int achk   = (lane >> 4) * 16;
    const int brow_l = (lane & 7) + (lane >> 4) * 8;
    const int bchk   = ((lane >> 3) & 1) * 16;
    const int qr     = lane >> 2;
    const int qc     = (lane & 3) * 2;

    uint32_t qfrag[4][2][4];
    float zacc[2][4][4];
    #pragma unroll
    for (int f = 0; f < 2; f++)
        #pragma unroll
        for (int j = 0; j < 4; j++)
            #pragma unroll
            for (int e = 0; e < 4; e++) zacc[f][j][e] = 0.f;

    #pragma unroll 1
    for (int it = 0; it < 32; it++) {
        if (it + 3 < 32) { CP_WAIT(2); } else { CP_WAIT(0); }
        __syncthreads();
        if (it + 3 < 32)
            attn_issue(sb + AKV + (uint32_t)((it + 3) & 3) * ASTG, khb, vtb, (it + 3) * 64, tid);
        const uint32_t sK = sb + AKV + (uint32_t)(it & 3) * ASTG;
        const uint32_t sV = sK + 8192u;

        if (it == 0) {
            #pragma unroll
            for (int kk = 0; kk < 4; kk++)
                #pragma unroll
                for (int f = 0; f < 2; f++)
                    ldm_x4(qfrag[kk][f], sb + AQ + SWZ(wm * 32 + f * 16 + arow_l, kk * 32 + achk));
        }

        // phase 1: s = q x k^T
        float sacc[2][4][4];
        #pragma unroll
        for (int f = 0; f < 2; f++)
            #pragma unroll
            for (int j = 0; j < 4; j++)
                #pragma unroll
                for (int e = 0; e < 4; e++) sacc[f][j][e] = 0.f;
        #pragma unroll
        for (int kk = 0; kk < 4; kk++) {
            #pragma unroll
            for (int g = 0; g < 2; g++) {
                uint32_t b4[4];
                ldm_x4(b4, sK + SWZ(wn * 32 + g * 16 + brow_l, kk * 32 + bchk));
                #pragma unroll
                for (int f = 0; f < 2; f++) {
                    mma16816(sacc[f][g * 2 + 0], qfrag[kk][f], b4 + 0);
                    mma16816(sacc[f][g * 2 + 1], qfrag[kk][f], b4 + 2);
                }
            }
        }
        // quantize s -> 2 limb planes, packed u32 stores
        #pragma unroll
        for (int f = 0; f < 2; f++)
            #pragma unroll
            for (int j = 0; j < 4; j++)
                #pragma unroll
                for (int rs = 0; rs < 2; rs++) {
                    int row = wm * 32 + f * 16 + qr + rs * 8;
                    int colb = (wn * 32 + j * 8 + qc) * 2;
                    float s0 = qround8(sacc[f][j][rs * 2 + 0]);
                    float s1 = qround8(sacc[f][j][rs * 2 + 1]);
                    __half h0 = __float2half_rn(s0);
                    __half h1 = __float2half_rn(s1);
                    __half l0 = __float2half_rn(s0 - __half2float(h0));
                    __half l1 = __float2half_rn(s1 - __half2float(h1));
                    *(uint32_t*)(smem + ASH + SWZ(row, colb)) = packu32(h0, h1);
                    *(uint32_t*)(smem + ASL + SWZ(row, colb)) = packu32(l0, l1);
                }
        __syncthreads();

        // phase 2: z += s x v; V frags shared across both s-limb planes
        #pragma unroll
        for (int kk = 0; kk < 4; kk++) {
            uint32_t bv[2][4];
            #pragma unroll
            for (int g = 0; g < 2; g++)
                ldm_x4(bv[g], sV + SWZ(wn * 32 + g * 16 + brow_l, kk * 32 + bchk));
            #pragma unroll
            for (int plane = 0; plane < 2; plane++) {
                uint32_t sp = sb + (plane ? ASL : ASH);
                uint32_t a[2][4];
                #pragma unroll
                for (int f = 0; f < 2; f++)
                    ldm_x4(a[f], sp + SWZ(wm * 32 + f * 16 + arow_l, kk * 32 + achk));
                #pragma unroll
                for (int g = 0; g < 2; g++)
                    #pragma unroll
                    for (int f = 0; f < 2; f++) {
                        mma16816(zacc[f][g * 2 + 0], a[f], bv[g] + 0);
                        mma16816(zacc[f][g * 2 + 1], a[f], bv[g] + 2);
                    }
            }
        }
    }

    // epilogue: quantize z (clamped), write hi/lo planes for proj
    const int b = bh / H_, h = bh - b * H_;
    #pragma unroll
    for (int f = 0; f < 2; f++)
        #pragma unroll
        for (int j = 0; j < 4; j++)
            #pragma unroll
            for (int rs = 0; rs < 2; rs++) {
                int n = q0 + wm * 32 + f * 16 + qr + rs * 8;
                int e = wn * 32 + j * 8 + qc;   // even
                float z0 = q16_8c(zacc[f][j][rs * 2 + 0]);
                float z1 = q16_8c(zacc[f][j][rs * 2 + 1]);
                __half h0 = __float2half_rn(z0);
                __half h1 = __float2half_rn(z1);
                __half l0 = __float2half_rn(z0 - __half2float(h0));
                __half l1 = __float2half_rn(z1 - __half2float(h1));
                long off = (long)(b * N_ + n) * DIM_ + h * DH_ + e;
                *(uint32_t*)(g_zh + off)  = packu32(h0, h1);
                *(uint32_t*)(g_zlo + off) = packu32(l0, l1);
            }
}

// ---------------- launch ----------------
extern "C" void kernel_launch(void* const* d_in, const int* in_sizes, int n_in,
                              void* d_out, int out_size) {
    const float* q_in = (const float*)d_in[0];
    const float* wqkv = (const float*)d_in[1];
    const float* bqkv = (const float*)d_in[2];
    const float* wp   = (const float*)d_in[3];
    const float* bp   = (const float*)d_in[4];
    float* out = (float*)d_out;

    const long total4 = ((long)M1 * DIM_ + (long)NC1 * DIM_ + (long)DIM_ * DIM_ + NC1 + DIM_) / 4;
    prep_kernel<<<(unsigned)((total4 + 255) / 256), 256>>>(q_in, wqkv, bqkv, wp, bp);

    const int qkv_smem = 2 * QSTG;   // 98304 -> 2 CTA/SM
    cudaFuncSetAttribute(gemm_qkv_tc, cudaFuncAttributeMaxDynamicSharedMemorySize, qkv_smem);
    gemm_qkv_tc<<<dim3(NC1 / 128, M1 / 128), 256, qkv_smem>>>();        // (18, 32)

    cudaFuncSetAttribute(attn_tc_kernel, cudaFuncAttributeMaxDynamicSharedMemorySize, ATTN_SMEM);
    attn_tc_kernel<<<dim3(N_ / 128, B_ * H_), 256, ATTN_SMEM>>>();      // (16, 24)

    const int proj_smem = 3 * PSTG;   // 98304 -> 2 CTA/SM
    cudaFuncSetAttribute(gemm_proj_tc, cudaFuncAttributeMaxDynamicSharedMemorySize, proj_smem);
    gemm_proj_tc<<<dim3(DIM_ / 128, M1 / 64), 256, proj_smem>>>(out);   // (6, 64)
}